// round 1
// baseline (speedup 1.0000x reference)
#include <cuda_runtime.h>
#include <cuda_bf16.h>
#include <math_constants.h>

// ---------------- problem constants ----------------
#define NN   4096
#define DD   128
#define HH   4
#define DHH  32
#define DFF  2048
#define HID  256
#define OUTD 64
#define EE   131072
#define LNEPS 1e-5f

// ---------------- scratch (static device memory; no allocation allowed) ---
__device__ float g_qkv[NN * 384];
__device__ float g_ctx[NN * DD];
__device__ float g_tmp[NN * DD];     // attn_out, then ffn2 output
__device__ float g_y[NN * DD];
__device__ float g_mid[NN * DFF];
__device__ float g_z[NN * DD];
__device__ float g_hw[NN * HID];     // pre-aggregation features (max width 256)
__device__ float g_h1[NN * HID];
__device__ float g_h2[NN * HID];
__device__ float g_dinv[NN];
__device__ int   g_cnt[NN];
__device__ int   g_rowptr[NN + 1];
__device__ int   g_fillpos[NN];
__device__ int   g_col[EE];

// ---------------- generic SGEMM: C[M,Nc] = A[M,K] * B[Nc,K]^T (+bias)(+relu)
// BM=BN=64, BK=16, 256 threads, 4x4 per thread. All dims divide tiles.
__global__ void gemm_kernel(const float* __restrict__ A,
                            const float* __restrict__ B,
                            const float* __restrict__ bias,
                            float* __restrict__ C,
                            int M, int Nc, int K, int relu)
{
    __shared__ float As[16][64];
    __shared__ float Bs[16][64];
    int tid = threadIdx.x;
    int tx = tid & 15, ty = tid >> 4;
    int row0 = blockIdx.y * 64, col0 = blockIdx.x * 64;

    int lr = tid >> 2;          // 0..63 row within tile
    int lk = (tid & 3) * 4;     // 0,4,8,12

    float acc[4][4];
#pragma unroll
    for (int i = 0; i < 4; i++)
#pragma unroll
        for (int j = 0; j < 4; j++) acc[i][j] = 0.0f;

    for (int k0 = 0; k0 < K; k0 += 16) {
        float4 a = *(const float4*)(A + (size_t)(row0 + lr) * K + k0 + lk);
        As[lk + 0][lr] = a.x; As[lk + 1][lr] = a.y;
        As[lk + 2][lr] = a.z; As[lk + 3][lr] = a.w;
        float4 b = *(const float4*)(B + (size_t)(col0 + lr) * K + k0 + lk);
        Bs[lk + 0][lr] = b.x; Bs[lk + 1][lr] = b.y;
        Bs[lk + 2][lr] = b.z; Bs[lk + 3][lr] = b.w;
        __syncthreads();
#pragma unroll
        for (int k = 0; k < 16; k++) {
            float4 av = *(const float4*)&As[k][ty * 4];
            float4 bv = *(const float4*)&Bs[k][tx * 4];
            acc[0][0] += av.x * bv.x; acc[0][1] += av.x * bv.y;
            acc[0][2] += av.x * bv.z; acc[0][3] += av.x * bv.w;
            acc[1][0] += av.y * bv.x; acc[1][1] += av.y * bv.y;
            acc[1][2] += av.y * bv.z; acc[1][3] += av.y * bv.w;
            acc[2][0] += av.z * bv.x; acc[2][1] += av.z * bv.y;
            acc[2][2] += av.z * bv.z; acc[2][3] += av.z * bv.w;
            acc[3][0] += av.w * bv.x; acc[3][1] += av.w * bv.y;
            acc[3][2] += av.w * bv.z; acc[3][3] += av.w * bv.w;
        }
        __syncthreads();
    }

    float4 bb = make_float4(0.f, 0.f, 0.f, 0.f);
    if (bias) bb = *(const float4*)&bias[col0 + tx * 4];
#pragma unroll
    for (int i = 0; i < 4; i++) {
        float4 o;
        o.x = acc[i][0] + bb.x; o.y = acc[i][1] + bb.y;
        o.z = acc[i][2] + bb.z; o.w = acc[i][3] + bb.w;
        if (relu) {
            o.x = fmaxf(o.x, 0.f); o.y = fmaxf(o.y, 0.f);
            o.z = fmaxf(o.z, 0.f); o.w = fmaxf(o.w, 0.f);
        }
        *(float4*)&C[(size_t)(row0 + ty * 4 + i) * Nc + col0 + tx * 4] = o;
    }
}

// ---------------- attention: flash-style, 1 thread = 1 query row ----------
// grid (N/64, H), 64 threads. K/V tiles of 32 keys staged in SMEM; reads are
// warp-broadcast (all lanes read the same key row) -> conflict-free.
__global__ void __launch_bounds__(64) attn_kernel(const float* __restrict__ qkv,
                                                  float* __restrict__ ctx)
{
    const int h = blockIdx.y;
    const int n = blockIdx.x * 64 + threadIdx.x;
    const int tid = threadIdx.x;
    const float SCALE = 0.17677669529663687f;  // 1/sqrt(32)

    __shared__ float sK[32][32];
    __shared__ float sV[32][32];

    float q[32], acc[32];
    {
        const float* qp = qkv + (size_t)n * 384 + h * 32;
#pragma unroll
        for (int c = 0; c < 8; c++) {
            float4 v = *(const float4*)(qp + c * 4);
            q[c * 4 + 0] = v.x; q[c * 4 + 1] = v.y; q[c * 4 + 2] = v.z; q[c * 4 + 3] = v.w;
        }
    }
#pragma unroll
    for (int d = 0; d < 32; d++) acc[d] = 0.0f;
    float m = -CUDART_INF_F, l = 0.0f;

    const int koff = DD + h * 32;       // K block offset within qkv row
    const int voff = 2 * DD + h * 32;   // V block offset

    for (int kt = 0; kt < NN / 32; kt++) {
        // load 32 keys + 32 values (each 32 floats) with 64 threads
        for (int i = tid; i < 256; i += 64) {
            int j = i >> 3, c = i & 7;
            const float* kp = qkv + (size_t)(kt * 32 + j) * 384;
            *(float4*)&sK[j][c * 4] = *(const float4*)(kp + koff + c * 4);
            *(float4*)&sV[j][c * 4] = *(const float4*)(kp + voff + c * 4);
        }
        __syncthreads();

        float s[32];
        float tmax = -CUDART_INF_F;
#pragma unroll 4
        for (int j = 0; j < 32; j++) {
            float d0 = 0.0f;
#pragma unroll
            for (int d = 0; d < 32; d++) d0 += q[d] * sK[j][d];
            d0 *= SCALE;
            s[j] = d0;
            tmax = fmaxf(tmax, d0);
        }
        float newm = fmaxf(m, tmax);
        float f = __expf(m - newm);   // 0 when m == -inf
        m = newm;
        l *= f;
#pragma unroll
        for (int d = 0; d < 32; d++) acc[d] *= f;
#pragma unroll 4
        for (int j = 0; j < 32; j++) {
            float p = __expf(s[j] - m);
            l += p;
#pragma unroll
            for (int d = 0; d < 32; d++) acc[d] += p * sV[j][d];
        }
        __syncthreads();
    }

    float inv = 1.0f / l;
    float* op = ctx + (size_t)n * DD + h * 32;
#pragma unroll
    for (int c = 0; c < 8; c++) {
        float4 v;
        v.x = acc[c * 4 + 0] * inv; v.y = acc[c * 4 + 1] * inv;
        v.z = acc[c * 4 + 2] * inv; v.w = acc[c * 4 + 3] * inv;
        *(float4*)(op + c * 4) = v;
    }
}

// ---------------- residual + LayerNorm (row of 128) -----------------------
__global__ void ln_kernel(const float* __restrict__ x, const float* __restrict__ r,
                          const float* __restrict__ g, const float* __restrict__ b,
                          float* __restrict__ out)
{
    int n = blockIdx.x, t = threadIdx.x;
    int lane = t & 31, w = t >> 5;
    float v = x[(size_t)n * DD + t] + r[(size_t)n * DD + t];

    __shared__ float red[8];
    float s = v;
#pragma unroll
    for (int off = 16; off > 0; off >>= 1) s += __shfl_xor_sync(0xffffffffu, s, off);
    if (lane == 0) red[w] = s;
    __syncthreads();
    float mu = (red[0] + red[1] + red[2] + red[3]) * (1.0f / DD);

    float d = v - mu;
    float sq = d * d;
#pragma unroll
    for (int off = 16; off > 0; off >>= 1) sq += __shfl_xor_sync(0xffffffffu, sq, off);
    if (lane == 0) red[4 + w] = sq;
    __syncthreads();
    float var = (red[4] + red[5] + red[6] + red[7]) * (1.0f / DD);

    out[(size_t)n * DD + t] = d * rsqrtf(var + LNEPS) * g[t] + b[t];
}

// ---------------- GCN graph preprocessing ---------------------------------
__global__ void zero_cnt_kernel() {
    int i = blockIdx.x * blockDim.x + threadIdx.x;
    if (i < NN) g_cnt[i] = 0;
}
__global__ void count_kernel(const int* __restrict__ dst) {
    int e = blockIdx.x * blockDim.x + threadIdx.x;
    if (e < EE) atomicAdd(&g_cnt[dst[e]], 1);
}
__global__ void dinv_kernel() {
    int i = blockIdx.x * blockDim.x + threadIdx.x;
    if (i < NN) g_dinv[i] = rsqrtf((float)g_cnt[i] + 1.0f);  // +1 for self loop
}
// single-block scan over 4096 counts -> rowptr / fillpos
__global__ void scan_kernel() {
    __shared__ int sh[1024];
    int t = threadIdx.x;
    int base = t * 4;
    int c0 = g_cnt[base + 0], c1 = g_cnt[base + 1];
    int c2 = g_cnt[base + 2], c3 = g_cnt[base + 3];
    int local = c0 + c1 + c2 + c3;
    sh[t] = local;
    __syncthreads();
    for (int off = 1; off < 1024; off <<= 1) {
        int v = (t >= off) ? sh[t - off] : 0;
        __syncthreads();
        sh[t] += v;
        __syncthreads();
    }
    int excl = sh[t] - local;
    int p0 = excl, p1 = excl + c0, p2 = p1 + c1, p3 = p2 + c2;
    g_rowptr[base + 0] = p0; g_rowptr[base + 1] = p1;
    g_rowptr[base + 2] = p2; g_rowptr[base + 3] = p3;
    g_fillpos[base + 0] = p0; g_fillpos[base + 1] = p1;
    g_fillpos[base + 2] = p2; g_fillpos[base + 3] = p3;
    if (t == 1023) g_rowptr[NN] = excl + local;
}
__global__ void fill_kernel(const int* __restrict__ src, const int* __restrict__ dst) {
    int e = blockIdx.x * blockDim.x + threadIdx.x;
    if (e < EE) {
        int d = dst[e];
        int pos = atomicAdd(&g_fillpos[d], 1);
        g_col[pos] = src[e];
    }
}

// ---------------- GCN aggregation: gather over CSR (no atomics) ------------
// out[r] = relu?( sum_{e: dst=r} hw[src]*dinv[src]*dinv[r] + hw[r]*dinv[r]^2 + bias )
template<int F, bool RELU>
__global__ void gather_kernel(const float* __restrict__ hw,
                              const float* __restrict__ bias,
                              float* __restrict__ out)
{
    constexpr int TPR = F / 4;          // threads per row (float4 lanes)
    constexpr int RPB = 256 / TPR;      // rows per block
    int tid = threadIdx.x;
    int r = blockIdx.x * RPB + tid / TPR;
    int lane = tid % TPR;
    const float4* hw4 = (const float4*)hw;

    float dr = g_dinv[r];
    float4 acc = hw4[(size_t)r * TPR + lane];
    float self = dr * dr;
    acc.x *= self; acc.y *= self; acc.z *= self; acc.w *= self;

    int p1 = g_rowptr[r + 1];
    for (int p = g_rowptr[r]; p < p1; p++) {
        int s = g_col[p];
        float nrm = g_dinv[s] * dr;
        float4 hv = hw4[(size_t)s * TPR + lane];
        acc.x += nrm * hv.x; acc.y += nrm * hv.y;
        acc.z += nrm * hv.z; acc.w += nrm * hv.w;
    }
    float4 bb = *(const float4*)&bias[lane * 4];
    acc.x += bb.x; acc.y += bb.y; acc.z += bb.z; acc.w += bb.w;
    if (RELU) {
        acc.x = fmaxf(acc.x, 0.f); acc.y = fmaxf(acc.y, 0.f);
        acc.z = fmaxf(acc.z, 0.f); acc.w = fmaxf(acc.w, 0.f);
    }
    *(float4*)&out[(size_t)r * F + lane * 4] = acc;
}

// ---------------- launch ---------------------------------------------------
extern "C" void kernel_launch(void* const* d_in, const int* in_sizes, int n_in,
                              void* d_out, int out_size)
{
    const float* x          = (const float*)d_in[0];
    const int*   edge_index = (const int*)  d_in[1];
    const float* in_proj_w  = (const float*)d_in[2];
    const float* in_proj_b  = (const float*)d_in[3];
    const float* out_proj_w = (const float*)d_in[4];
    const float* out_proj_b = (const float*)d_in[5];
    const float* ln1_g      = (const float*)d_in[6];
    const float* ln1_b      = (const float*)d_in[7];
    const float* ffn_w1     = (const float*)d_in[8];
    const float* ffn_b1     = (const float*)d_in[9];
    const float* ffn_w2     = (const float*)d_in[10];
    const float* ffn_b2     = (const float*)d_in[11];
    const float* ln2_g      = (const float*)d_in[12];
    const float* ln2_b      = (const float*)d_in[13];
    const float* gcn1_w     = (const float*)d_in[14];
    const float* gcn1_b     = (const float*)d_in[15];
    const float* gcn2_w     = (const float*)d_in[16];
    const float* gcn2_b     = (const float*)d_in[17];
    const float* gcn3_w     = (const float*)d_in[18];
    const float* gcn3_b     = (const float*)d_in[19];
    float* out = (float*)d_out;

    const int* src = edge_index;
    const int* dst = edge_index + EE;

    float *p_qkv, *p_ctx, *p_tmp, *p_y, *p_mid, *p_z, *p_hw, *p_h1, *p_h2;
    cudaGetSymbolAddress((void**)&p_qkv, g_qkv);
    cudaGetSymbolAddress((void**)&p_ctx, g_ctx);
    cudaGetSymbolAddress((void**)&p_tmp, g_tmp);
    cudaGetSymbolAddress((void**)&p_y,   g_y);
    cudaGetSymbolAddress((void**)&p_mid, g_mid);
    cudaGetSymbolAddress((void**)&p_z,   g_z);
    cudaGetSymbolAddress((void**)&p_hw,  g_hw);
    cudaGetSymbolAddress((void**)&p_h1,  g_h1);
    cudaGetSymbolAddress((void**)&p_h2,  g_h2);

    // ---- transformer encoder layer ----
    gemm_kernel<<<dim3(384 / 64, NN / 64), 256>>>(x, in_proj_w, in_proj_b, p_qkv,
                                                  NN, 384, DD, 0);
    attn_kernel<<<dim3(NN / 64, HH), 64>>>(p_qkv, p_ctx);
    gemm_kernel<<<dim3(DD / 64, NN / 64), 256>>>(p_ctx, out_proj_w, out_proj_b, p_tmp,
                                                 NN, DD, DD, 0);
    ln_kernel<<<NN, DD>>>(x, p_tmp, ln1_g, ln1_b, p_y);
    gemm_kernel<<<dim3(DFF / 64, NN / 64), 256>>>(p_y, ffn_w1, ffn_b1, p_mid,
                                                  NN, DFF, DD, 1);
    gemm_kernel<<<dim3(DD / 64, NN / 64), 256>>>(p_mid, ffn_w2, ffn_b2, p_tmp,
                                                 NN, DD, DFF, 0);
    ln_kernel<<<NN, DD>>>(p_y, p_tmp, ln2_g, ln2_b, p_z);

    // ---- graph preprocessing (CSR by dst) ----
    zero_cnt_kernel<<<NN / 256, 256>>>();
    count_kernel<<<EE / 256, 256>>>(dst);
    dinv_kernel<<<NN / 256, 256>>>();
    scan_kernel<<<1, 1024>>>();
    fill_kernel<<<EE / 256, 256>>>(src, dst);

    // ---- GCN layer 1 (128 -> 256, relu) ----
    gemm_kernel<<<dim3(HID / 64, NN / 64), 256>>>(p_z, gcn1_w, nullptr, p_hw,
                                                  NN, HID, DD, 0);
    gather_kernel<HID, true><<<NN / 4, 256>>>(p_hw, gcn1_b, p_h1);

    // ---- GCN layer 2 (256 -> 256, relu) ----
    gemm_kernel<<<dim3(HID / 64, NN / 64), 256>>>(p_h1, gcn2_w, nullptr, p_hw,
                                                  NN, HID, HID, 0);
    gather_kernel<HID, true><<<NN / 4, 256>>>(p_hw, gcn2_b, p_h2);

    // ---- GCN layer 3 (256 -> 64) ----
    gemm_kernel<<<dim3(OUTD / 64, NN / 64), 256>>>(p_h2, gcn3_w, nullptr, p_hw,
                                                   NN, OUTD, HID, 0);
    gather_kernel<OUTD, false><<<NN / 16, 256>>>(p_hw, gcn3_b, out);
}

// round 2
// speedup vs baseline: 1.6492x; 1.6492x over previous
#include <cuda_runtime.h>
#include <cuda_bf16.h>
#include <math_constants.h>

// ---------------- problem constants ----------------
#define NN   4096
#define DD   128
#define HH   4
#define DHH  32
#define DFF  2048
#define HID  256
#define OUTD 64
#define EE   131072
#define LNEPS 1e-5f
#define ASPLIT 4
#define FSPLIT 4

typedef unsigned long long ull;

// ---------------- f32x2 helpers (FFMA2 path: full-rate fp32 on sm_103a) ----
__device__ __forceinline__ ull ffma2(ull a, ull b, ull c) {
    ull d; asm("fma.rn.f32x2 %0, %1, %2, %3;" : "=l"(d) : "l"(a), "l"(b), "l"(c));
    return d;
}
__device__ __forceinline__ ull add2(ull a, ull b) {
    ull d; asm("add.rn.f32x2 %0, %1, %2;" : "=l"(d) : "l"(a), "l"(b));
    return d;
}
__device__ __forceinline__ ull mul2(ull a, ull b) {
    ull d; asm("mul.rn.f32x2 %0, %1, %2;" : "=l"(d) : "l"(a), "l"(b));
    return d;
}
__device__ __forceinline__ ull pack2(float lo, float hi) {
    ull d; asm("mov.b64 %0, {%1, %2};" : "=l"(d) : "f"(lo), "f"(hi));
    return d;
}
__device__ __forceinline__ void unpack2(ull v, float& lo, float& hi) {
    asm("mov.b64 {%0, %1}, %2;" : "=f"(lo), "=f"(hi) : "l"(v));
}
__device__ __forceinline__ ull dup2(float x) { return pack2(x, x); }

__device__ __forceinline__ void lds2(ull& x, ull& y, unsigned a) {
    asm volatile("ld.shared.v2.u64 {%0,%1}, [%2];" : "=l"(x), "=l"(y) : "r"(a));
}
__device__ __forceinline__ unsigned smem_u32(const void* p) {
    unsigned a;
    asm("{ .reg .u64 t; cvta.to.shared.u64 t, %1; cvt.u32.u64 %0, t; }"
        : "=r"(a) : "l"(p));
    return a;
}

// ---------------- scratch ----------------
__device__ float g_qkv[NN * 384];
__device__ float g_ctx[NN * DD];
__device__ float g_tmp[NN * DD];
__device__ float g_y[NN * DD];
__device__ float g_mid[NN * DFF];
__device__ float g_z[NN * DD];
__device__ float g_f2[FSPLIT * NN * DD];
__device__ float g_hw[NN * HID];
__device__ float g_h1[NN * HID];
__device__ float g_h2[NN * HID];
__device__ float g_pm[HH * NN * ASPLIT];
__device__ float g_pl[HH * NN * ASPLIT];
__device__ float g_pacc[HH * NN * ASPLIT * 32];
__device__ float g_dinv[NN];
__device__ int   g_cnt[NN];
__device__ int   g_rowptr[NN + 1];
__device__ int   g_fillpos[NN];
__device__ int   g_col[EE];

// ---------------- SGEMM: C = A[M,K] * B[Nc,K]^T (+bias)(+relu) -------------
// BM=128, BN=64, BK=16, 256 threads, 8x4 per thread via FFMA2 (pairs along M).
// Optional K-split via blockIdx.z (kslice = K per slice); slice z writes
// C + z*M*Nc. bias/relu only valid when unsplit.
__global__ void __launch_bounds__(256) gemm2_kernel(
    const float* __restrict__ A, const float* __restrict__ B,
    const float* __restrict__ bias, float* __restrict__ C,
    int M, int Nc, int K, int relu, int kslice)
{
    __shared__ float As[16][128];
    __shared__ float Bs[16][64];
    const int tid = threadIdx.x;
    const int row0 = blockIdx.y * 128, col0 = blockIdx.x * 64;
    const int kbeg = blockIdx.z * kslice, kend = kbeg + kslice;
    C += (size_t)blockIdx.z * M * Nc;

    const int lrA = tid >> 1, lkA = (tid & 1) * 8;
    const int lrB = tid >> 2, lkB = (tid & 3) * 4;
    const int tx = tid & 15, ty = tid >> 4;

    const unsigned aBase = smem_u32(As) + ty * 32;   // &As[0][ty*8]
    ull acc[4][4] = {};

    for (int k0 = kbeg; k0 < kend; k0 += 16) {
        const float* ap = A + (size_t)(row0 + lrA) * K + k0 + lkA;
        float4 a0 = *(const float4*)ap;
        float4 a1 = *(const float4*)(ap + 4);
        As[lkA + 0][lrA] = a0.x; As[lkA + 1][lrA] = a0.y;
        As[lkA + 2][lrA] = a0.z; As[lkA + 3][lrA] = a0.w;
        As[lkA + 4][lrA] = a1.x; As[lkA + 5][lrA] = a1.y;
        As[lkA + 6][lrA] = a1.z; As[lkA + 7][lrA] = a1.w;
        float4 b = *(const float4*)(B + (size_t)(col0 + lrB) * K + k0 + lkB);
        Bs[lkB + 0][lrB] = b.x; Bs[lkB + 1][lrB] = b.y;
        Bs[lkB + 2][lrB] = b.z; Bs[lkB + 3][lrB] = b.w;
        __syncthreads();
#pragma unroll
        for (int k = 0; k < 16; k++) {
            ull a01, a23, a45, a67;
            lds2(a01, a23, aBase + k * 512);
            lds2(a45, a67, aBase + k * 512 + 16);
            float4 bv = *(const float4*)&Bs[k][tx * 4];
            ull b0 = dup2(bv.x), b1 = dup2(bv.y), b2 = dup2(bv.z), b3 = dup2(bv.w);
            acc[0][0] = ffma2(a01, b0, acc[0][0]);
            acc[0][1] = ffma2(a01, b1, acc[0][1]);
            acc[0][2] = ffma2(a01, b2, acc[0][2]);
            acc[0][3] = ffma2(a01, b3, acc[0][3]);
            acc[1][0] = ffma2(a23, b0, acc[1][0]);
            acc[1][1] = ffma2(a23, b1, acc[1][1]);
            acc[1][2] = ffma2(a23, b2, acc[1][2]);
            acc[1][3] = ffma2(a23, b3, acc[1][3]);
            acc[2][0] = ffma2(a45, b0, acc[2][0]);
            acc[2][1] = ffma2(a45, b1, acc[2][1]);
            acc[2][2] = ffma2(a45, b2, acc[2][2]);
            acc[2][3] = ffma2(a45, b3, acc[2][3]);
            acc[3][0] = ffma2(a67, b0, acc[3][0]);
            acc[3][1] = ffma2(a67, b1, acc[3][1]);
            acc[3][2] = ffma2(a67, b2, acc[3][2]);
            acc[3][3] = ffma2(a67, b3, acc[3][3]);
        }
        __syncthreads();
    }

    float4 bb = make_float4(0.f, 0.f, 0.f, 0.f);
    if (bias) bb = *(const float4*)&bias[col0 + tx * 4];
#pragma unroll
    for (int ip = 0; ip < 4; ip++) {
        float lo0, hi0, lo1, hi1, lo2, hi2, lo3, hi3;
        unpack2(acc[ip][0], lo0, hi0);
        unpack2(acc[ip][1], lo1, hi1);
        unpack2(acc[ip][2], lo2, hi2);
        unpack2(acc[ip][3], lo3, hi3);
        float4 e = make_float4(lo0 + bb.x, lo1 + bb.y, lo2 + bb.z, lo3 + bb.w);
        float4 o = make_float4(hi0 + bb.x, hi1 + bb.y, hi2 + bb.z, hi3 + bb.w);
        if (relu) {
            e.x = fmaxf(e.x, 0.f); e.y = fmaxf(e.y, 0.f);
            e.z = fmaxf(e.z, 0.f); e.w = fmaxf(e.w, 0.f);
            o.x = fmaxf(o.x, 0.f); o.y = fmaxf(o.y, 0.f);
            o.z = fmaxf(o.z, 0.f); o.w = fmaxf(o.w, 0.f);
        }
        int r = row0 + ty * 8 + ip * 2;
        *(float4*)&C[(size_t)r * Nc + col0 + tx * 4] = e;
        *(float4*)&C[(size_t)(r + 1) * Nc + col0 + tx * 4] = o;
    }
}

// ---------------- attention: flash-style split-K, FFMA2 inner loops -------
// grid (N/64, H, ASPLIT), 64 threads; each thread = 1 query over NN/ASPLIT keys.
__global__ void __launch_bounds__(64) attn_kernel(const float* __restrict__ qkv,
                                                  float* __restrict__ pm,
                                                  float* __restrict__ pl,
                                                  float* __restrict__ pacc)
{
    const int h = blockIdx.y, z = blockIdx.z;
    const int n = blockIdx.x * 64 + threadIdx.x;
    const int tid = threadIdx.x;
    const float SCALE = 0.17677669529663687f;  // 1/sqrt(32)

    __shared__ float sK[32][32];
    __shared__ float sV[32][32];
    const unsigned sKa = smem_u32(sK);
    const unsigned sVa = smem_u32(sV);

    ull q2[16], acc2[16];
    {
        const float* qp = qkv + (size_t)n * 384 + h * 32;
#pragma unroll
        for (int c = 0; c < 8; c++) {
            float4 v = *(const float4*)(qp + c * 4);
            q2[c * 2 + 0] = pack2(v.x, v.y);
            q2[c * 2 + 1] = pack2(v.z, v.w);
        }
    }
#pragma unroll
    for (int d = 0; d < 16; d++) acc2[d] = 0ull;
    float m = -CUDART_INF_F, l = 0.0f;

    const int koff = DD + h * 32;
    const int voff = 2 * DD + h * 32;
    const int kt0 = z * (NN / ASPLIT / 32);
    const int kt1 = kt0 + (NN / ASPLIT / 32);

    for (int kt = kt0; kt < kt1; kt++) {
        for (int i = tid; i < 256; i += 64) {
            int j = i >> 3, c = i & 7;
            const float* kp = qkv + (size_t)(kt * 32 + j) * 384;
            *(float4*)&sK[j][c * 4] = *(const float4*)(kp + koff + c * 4);
            *(float4*)&sV[j][c * 4] = *(const float4*)(kp + voff + c * 4);
        }
        __syncthreads();

        float s[32];
        float tmax = -CUDART_INF_F;
#pragma unroll 4
        for (int j = 0; j < 32; j++) {
            ull k0, k1, k2, k3;
            ull t0 = 0ull, t1 = 0ull;
            unsigned base = sKa + j * 128;
#pragma unroll
            for (int c = 0; c < 4; c++) {
                lds2(k0, k1, base + c * 32);
                lds2(k2, k3, base + c * 32 + 16);
                t0 = ffma2(q2[c * 4 + 0], k0, t0);
                t1 = ffma2(q2[c * 4 + 1], k1, t1);
                t0 = ffma2(q2[c * 4 + 2], k2, t0);
                t1 = ffma2(q2[c * 4 + 3], k3, t1);
            }
            ull t = add2(t0, t1);
            float lo, hi;
            unpack2(t, lo, hi);
            float d0 = (lo + hi) * SCALE;
            s[j] = d0;
            tmax = fmaxf(tmax, d0);
        }
        float newm = fmaxf(m, tmax);
        float f = __expf(m - newm);
        m = newm;
        l *= f;
        ull f2 = dup2(f);
#pragma unroll
        for (int d = 0; d < 16; d++) acc2[d] = mul2(acc2[d], f2);
#pragma unroll 2
        for (int j = 0; j < 32; j++) {
            float p = __expf(s[j] - m);
            l += p;
            ull pd = dup2(p);
            unsigned base = sVa + j * 128;
            ull v0, v1, v2, v3;
#pragma unroll
            for (int c = 0; c < 4; c++) {
                lds2(v0, v1, base + c * 32);
                lds2(v2, v3, base + c * 32 + 16);
                acc2[c * 4 + 0] = ffma2(pd, v0, acc2[c * 4 + 0]);
                acc2[c * 4 + 1] = ffma2(pd, v1, acc2[c * 4 + 1]);
                acc2[c * 4 + 2] = ffma2(pd, v2, acc2[c * 4 + 2]);
                acc2[c * 4 + 3] = ffma2(pd, v3, acc2[c * 4 + 3]);
            }
        }
        __syncthreads();
    }

    const int pi = (h * NN + n) * ASPLIT + z;
    pm[pi] = m;
    pl[pi] = l;
    float* op = pacc + (size_t)pi * 32;
#pragma unroll
    for (int d = 0; d < 16; d++) {
        float lo, hi;
        unpack2(acc2[d], lo, hi);
        op[d * 2 + 0] = lo;
        op[d * 2 + 1] = hi;
    }
}

// combine ASPLIT partials -> ctx
__global__ void attn_combine_kernel(const float* __restrict__ pm,
                                    const float* __restrict__ pl,
                                    const float* __restrict__ pacc,
                                    float* __restrict__ ctx)
{
    int t = blockIdx.x * 256 + threadIdx.x;   // 0 .. HH*NN-1
    int h = t >> 12, n = t & (NN - 1);
    int base = t * ASPLIT;
    float m = pm[base];
#pragma unroll
    for (int zz = 1; zz < ASPLIT; zz++) m = fmaxf(m, pm[base + zz]);
    float l = 0.f;
    float o[32];
#pragma unroll
    for (int d = 0; d < 32; d++) o[d] = 0.f;
#pragma unroll
    for (int zz = 0; zz < ASPLIT; zz++) {
        float w = __expf(pm[base + zz] - m);
        l += pl[base + zz] * w;
        const float* pa = pacc + (size_t)(base + zz) * 32;
#pragma unroll
        for (int d = 0; d < 32; d++) o[d] += w * pa[d];
    }
    float inv = 1.0f / l;
    float* op = ctx + (size_t)n * DD + h * 32;
#pragma unroll
    for (int d = 0; d < 32; d++) op[d] = o[d] * inv;
}

// ---------------- residual + LayerNorm -------------------------------------
__global__ void ln_kernel(const float* __restrict__ x, const float* __restrict__ r,
                          const float* __restrict__ g, const float* __restrict__ b,
                          float* __restrict__ out)
{
    int n = blockIdx.x, t = threadIdx.x;
    int lane = t & 31, w = t >> 5;
    float v = x[(size_t)n * DD + t] + r[(size_t)n * DD + t];

    __shared__ float red[8];
    float s = v;
#pragma unroll
    for (int off = 16; off > 0; off >>= 1) s += __shfl_xor_sync(0xffffffffu, s, off);
    if (lane == 0) red[w] = s;
    __syncthreads();
    float mu = (red[0] + red[1] + red[2] + red[3]) * (1.0f / DD);

    float d = v - mu;
    float sq = d * d;
#pragma unroll
    for (int off = 16; off > 0; off >>= 1) sq += __shfl_xor_sync(0xffffffffu, sq, off);
    if (lane == 0) red[4 + w] = sq;
    __syncthreads();
    float var = (red[4] + red[5] + red[6] + red[7]) * (1.0f / DD);

    out[(size_t)n * DD + t] = d * rsqrtf(var + LNEPS) * g[t] + b[t];
}

// residual + sum of FSPLIT partials + bias, then LayerNorm
__global__ void ln_sum4_kernel(const float* __restrict__ x,
                               const float* __restrict__ parts,
                               const float* __restrict__ fb,
                               const float* __restrict__ g,
                               const float* __restrict__ b,
                               float* __restrict__ out)
{
    int n = blockIdx.x, t = threadIdx.x;
    int lane = t & 31, w = t >> 5;
    size_t i = (size_t)n * DD + t;
    const size_t ps = (size_t)NN * DD;
    float v = x[i] + fb[t] + parts[i] + parts[i + ps] + parts[i + 2 * ps] + parts[i + 3 * ps];

    __shared__ float red[8];
    float s = v;
#pragma unroll
    for (int off = 16; off > 0; off >>= 1) s += __shfl_xor_sync(0xffffffffu, s, off);
    if (lane == 0) red[w] = s;
    __syncthreads();
    float mu = (red[0] + red[1] + red[2] + red[3]) * (1.0f / DD);

    float d = v - mu;
    float sq = d * d;
#pragma unroll
    for (int off = 16; off > 0; off >>= 1) sq += __shfl_xor_sync(0xffffffffu, sq, off);
    if (lane == 0) red[4 + w] = sq;
    __syncthreads();
    float var = (red[4] + red[5] + red[6] + red[7]) * (1.0f / DD);

    out[i] = d * rsqrtf(var + LNEPS) * g[t] + b[t];
}

// ---------------- GCN graph preprocessing ---------------------------------
__global__ void zero_cnt_kernel() {
    int i = blockIdx.x * blockDim.x + threadIdx.x;
    if (i < NN) g_cnt[i] = 0;
}
__global__ void count_kernel(const int* __restrict__ dst) {
    int e = blockIdx.x * blockDim.x + threadIdx.x;
    if (e < EE) atomicAdd(&g_cnt[dst[e]], 1);
}
__global__ void dinv_kernel() {
    int i = blockIdx.x * blockDim.x + threadIdx.x;
    if (i < NN) g_dinv[i] = rsqrtf((float)g_cnt[i] + 1.0f);
}
__global__ void scan_kernel() {
    __shared__ int sh[1024];
    int t = threadIdx.x;
    int base = t * 4;
    int c0 = g_cnt[base + 0], c1 = g_cnt[base + 1];
    int c2 = g_cnt[base + 2], c3 = g_cnt[base + 3];
    int local = c0 + c1 + c2 + c3;
    sh[t] = local;
    __syncthreads();
    for (int off = 1; off < 1024; off <<= 1) {
        int v = (t >= off) ? sh[t - off] : 0;
        __syncthreads();
        sh[t] += v;
        __syncthreads();
    }
    int excl = sh[t] - local;
    int p0 = excl, p1 = excl + c0, p2 = p1 + c1, p3 = p2 + c2;
    g_rowptr[base + 0] = p0; g_rowptr[base + 1] = p1;
    g_rowptr[base + 2] = p2; g_rowptr[base + 3] = p3;
    g_fillpos[base + 0] = p0; g_fillpos[base + 1] = p1;
    g_fillpos[base + 2] = p2; g_fillpos[base + 3] = p3;
    if (t == 1023) g_rowptr[NN] = excl + local;
}
__global__ void fill_kernel(const int* __restrict__ src, const int* __restrict__ dst) {
    int e = blockIdx.x * blockDim.x + threadIdx.x;
    if (e < EE) {
        int d = dst[e];
        int pos = atomicAdd(&g_fillpos[d], 1);
        g_col[pos] = src[e];
    }
}

// ---------------- GCN aggregation: gather over CSR -------------------------
template<int F, bool RELU>
__global__ void gather_kernel(const float* __restrict__ hw,
                              const float* __restrict__ bias,
                              float* __restrict__ out)
{
    constexpr int TPR = F / 4;
    constexpr int RPB = 256 / TPR;
    int tid = threadIdx.x;
    int r = blockIdx.x * RPB + tid / TPR;
    int lane = tid % TPR;
    const float4* hw4 = (const float4*)hw;

    float dr = g_dinv[r];
    float4 acc = hw4[(size_t)r * TPR + lane];
    float self = dr * dr;
    acc.x *= self; acc.y *= self; acc.z *= self; acc.w *= self;

    int p1 = g_rowptr[r + 1];
    for (int p = g_rowptr[r]; p < p1; p++) {
        int s = g_col[p];
        float nrm = g_dinv[s] * dr;
        float4 hv = hw4[(size_t)s * TPR + lane];
        acc.x += nrm * hv.x; acc.y += nrm * hv.y;
        acc.z += nrm * hv.z; acc.w += nrm * hv.w;
    }
    float4 bb = *(const float4*)&bias[lane * 4];
    acc.x += bb.x; acc.y += bb.y; acc.z += bb.z; acc.w += bb.w;
    if (RELU) {
        acc.x = fmaxf(acc.x, 0.f); acc.y = fmaxf(acc.y, 0.f);
        acc.z = fmaxf(acc.z, 0.f); acc.w = fmaxf(acc.w, 0.f);
    }
    *(float4*)&out[(size_t)r * F + lane * 4] = acc;
}

// ---------------- launch ---------------------------------------------------
extern "C" void kernel_launch(void* const* d_in, const int* in_sizes, int n_in,
                              void* d_out, int out_size)
{
    const float* x          = (const float*)d_in[0];
    const int*   edge_index = (const int*)  d_in[1];
    const float* in_proj_w  = (const float*)d_in[2];
    const float* in_proj_b  = (const float*)d_in[3];
    const float* out_proj_w = (const float*)d_in[4];
    const float* out_proj_b = (const float*)d_in[5];
    const float* ln1_g      = (const float*)d_in[6];
    const float* ln1_b      = (const float*)d_in[7];
    const float* ffn_w1     = (const float*)d_in[8];
    const float* ffn_b1     = (const float*)d_in[9];
    const float* ffn_w2     = (const float*)d_in[10];
    const float* ffn_b2     = (const float*)d_in[11];
    const float* ln2_g      = (const float*)d_in[12];
    const float* ln2_b      = (const float*)d_in[13];
    const float* gcn1_w     = (const float*)d_in[14];
    const float* gcn1_b     = (const float*)d_in[15];
    const float* gcn2_w     = (const float*)d_in[16];
    const float* gcn2_b     = (const float*)d_in[17];
    const float* gcn3_w     = (const float*)d_in[18];
    const float* gcn3_b     = (const float*)d_in[19];
    float* out = (float*)d_out;

    const int* src = edge_index;
    const int* dst = edge_index + EE;

    float *p_qkv, *p_ctx, *p_tmp, *p_y, *p_mid, *p_z, *p_f2, *p_hw, *p_h1, *p_h2;
    float *p_pm, *p_pl, *p_pacc;
    cudaGetSymbolAddress((void**)&p_qkv,  g_qkv);
    cudaGetSymbolAddress((void**)&p_ctx,  g_ctx);
    cudaGetSymbolAddress((void**)&p_tmp,  g_tmp);
    cudaGetSymbolAddress((void**)&p_y,    g_y);
    cudaGetSymbolAddress((void**)&p_mid,  g_mid);
    cudaGetSymbolAddress((void**)&p_z,    g_z);
    cudaGetSymbolAddress((void**)&p_f2,   g_f2);
    cudaGetSymbolAddress((void**)&p_hw,   g_hw);
    cudaGetSymbolAddress((void**)&p_h1,   g_h1);
    cudaGetSymbolAddress((void**)&p_h2,   g_h2);
    cudaGetSymbolAddress((void**)&p_pm,   g_pm);
    cudaGetSymbolAddress((void**)&p_pl,   g_pl);
    cudaGetSymbolAddress((void**)&p_pacc, g_pacc);

    // ---- transformer encoder layer ----
    gemm2_kernel<<<dim3(384 / 64, NN / 128), 256>>>(x, in_proj_w, in_proj_b, p_qkv,
                                                    NN, 384, DD, 0, DD);
    attn_kernel<<<dim3(NN / 64, HH, ASPLIT), 64>>>(p_qkv, p_pm, p_pl, p_pacc);
    attn_combine_kernel<<<HH * NN / 256, 256>>>(p_pm, p_pl, p_pacc, p_ctx);
    gemm2_kernel<<<dim3(DD / 64, NN / 128), 256>>>(p_ctx, out_proj_w, out_proj_b, p_tmp,
                                                   NN, DD, DD, 0, DD);
    ln_kernel<<<NN, DD>>>(x, p_tmp, ln1_g, ln1_b, p_y);
    gemm2_kernel<<<dim3(DFF / 64, NN / 128), 256>>>(p_y, ffn_w1, ffn_b1, p_mid,
                                                    NN, DFF, DD, 1, DD);
    gemm2_kernel<<<dim3(DD / 64, NN / 128, FSPLIT), 256>>>(p_mid, ffn_w2, nullptr, p_f2,
                                                           NN, DD, DFF, 0, DFF / FSPLIT);
    ln_sum4_kernel<<<NN, DD>>>(p_y, p_f2, ffn_b2, ln2_g, ln2_b, p_z);

    // ---- graph preprocessing (CSR by dst) ----
    zero_cnt_kernel<<<NN / 256, 256>>>();
    count_kernel<<<EE / 256, 256>>>(dst);
    dinv_kernel<<<NN / 256, 256>>>();
    scan_kernel<<<1, 1024>>>();
    fill_kernel<<<EE / 256, 256>>>(src, dst);

    // ---- GCN layers ----
    gemm2_kernel<<<dim3(HID / 64, NN / 128), 256>>>(p_z, gcn1_w, nullptr, p_hw,
                                                    NN, HID, DD, 0, DD);
    gather_kernel<HID, true><<<NN / 4, 256>>>(p_hw, gcn1_b, p_h1);

    gemm2_kernel<<<dim3(HID / 64, NN / 128), 256>>>(p_h1, gcn2_w, nullptr, p_hw,
                                                    NN, HID, HID, 0, HID);
    gather_kernel<HID, true><<<NN / 4, 256>>>(p_hw, gcn2_b, p_h2);

    gemm2_kernel<<<dim3(OUTD / 64, NN / 128), 256>>>(p_h2, gcn3_w, nullptr, p_hw,
                                                     NN, OUTD, HID, 0, HID);
    gather_kernel<OUTD, false><<<NN / 16, 256>>>(p_hw, gcn3_b, out);
}

// round 3
// speedup vs baseline: 2.8005x; 1.6981x over previous
#include <cuda_runtime.h>
#include <cuda_bf16.h>
#include <math_constants.h>

// ---------------- problem constants ----------------
#define NN   4096
#define DD   128
#define HH   4
#define DHH  32
#define DFF  2048
#define HID  256
#define OUTD 64
#define EE   131072
#define LNEPS 1e-5f
#define FSPLIT 4

typedef unsigned long long ull;
typedef unsigned u32;

// ---------------- f32x2 helpers (FFMA2 path for GCN gemms) -----------------
__device__ __forceinline__ ull ffma2(ull a, ull b, ull c) {
    ull d; asm("fma.rn.f32x2 %0, %1, %2, %3;" : "=l"(d) : "l"(a), "l"(b), "l"(c));
    return d;
}
__device__ __forceinline__ ull pack2(float lo, float hi) {
    ull d; asm("mov.b64 %0, {%1, %2};" : "=l"(d) : "f"(lo), "f"(hi));
    return d;
}
__device__ __forceinline__ void unpack2(ull v, float& lo, float& hi) {
    asm("mov.b64 {%0, %1}, %2;" : "=f"(lo), "=f"(hi) : "l"(v));
}
__device__ __forceinline__ ull dup2(float x) { return pack2(x, x); }
__device__ __forceinline__ void lds2(ull& x, ull& y, unsigned a) {
    asm volatile("ld.shared.v2.u64 {%0,%1}, [%2];" : "=l"(x), "=l"(y) : "r"(a));
}
__device__ __forceinline__ unsigned smem_u32(const void* p) {
    unsigned a;
    asm("{ .reg .u64 t; cvta.to.shared.u64 t, %1; cvt.u32.u64 %0, t; }"
        : "=r"(a) : "l"(p));
    return a;
}

// ---------------- tf32 mma helpers ----------------
__device__ __forceinline__ u32 f2tf(float x) {
    u32 u; asm("cvt.rna.tf32.f32 %0, %1;" : "=r"(u) : "f"(x));
    return u;
}
__device__ __forceinline__ void mma_tf32(float& d0, float& d1, float& d2, float& d3,
                                         u32 a0, u32 a1, u32 a2, u32 a3,
                                         u32 b0, u32 b1) {
    asm volatile(
        "mma.sync.aligned.m16n8k8.row.col.f32.tf32.tf32.f32 "
        "{%0,%1,%2,%3}, {%4,%5,%6,%7}, {%8,%9}, {%0,%1,%2,%3};\n"
        : "+f"(d0), "+f"(d1), "+f"(d2), "+f"(d3)
        : "r"(a0), "r"(a1), "r"(a2), "r"(a3), "r"(b0), "r"(b1));
}

// ---------------- scratch ----------------
__device__ float g_qkv[NN * 384];
__device__ float g_ctx[NN * DD];
__device__ float g_tmp[NN * DD];
__device__ float g_y[NN * DD];
__device__ float g_mid[NN * DFF];
__device__ float g_z[NN * DD];
__device__ float g_f2[FSPLIT * NN * DD];
__device__ float g_hw[NN * HID];
__device__ float g_h1[NN * HID];
__device__ float g_h2[NN * HID];
__device__ float g_dinv[NN];
__device__ int   g_cnt[NN];
__device__ int   g_rowptr[NN + 1];
__device__ int   g_fillpos[NN];
__device__ int   g_col[EE];

// ======================================================================
// tf32 tensor-core GEMM: C = A[M,K]*B[Nc,K]^T (+bias)(+relu)
// block tile 128x64, BK=32, 256 threads = 8 warps (4 along M x 2 along N),
// warp tile 32x32 = 2 m-tiles x 4 n-tiles of m16n8k8.
// Optional K-split (blockIdx.z, kslice); slice z writes C + z*M*Nc.
// ======================================================================
__global__ void __launch_bounds__(256) gemm_tc(
    const float* __restrict__ A, const float* __restrict__ B,
    const float* __restrict__ bias, float* __restrict__ C,
    int M, int Nc, int K, int relu, int kslice)
{
    __shared__ u32 As[32][136];   // [k][m], stride 136 -> frag bank (8t+g) distinct
    __shared__ u32 Bs[64][36];    // [n][k], stride 36  -> frag bank (4g+t) distinct

    const int tid = threadIdx.x;
    const int wid = tid >> 5, lane = tid & 31;
    const int g = lane >> 2, t = lane & 3;
    const int warp_m = wid >> 1, warp_n = wid & 1;
    const int row0 = blockIdx.y * 128, col0 = blockIdx.x * 64;
    const int kbeg = blockIdx.z * kslice, kend = kbeg + kslice;
    C += (size_t)blockIdx.z * M * Nc;

    // staging indices
    const int sm = tid & 127;            // A row within tile
    const int skb = (tid >> 7) * 16;     // A k base (0 or 16)
    const int sn = tid & 63;             // B row (n) within tile
    const int skb2 = (tid >> 6) * 8;     // B k base (0,8,16,24)

    float acc[2][4][4];
#pragma unroll
    for (int mt = 0; mt < 2; mt++)
#pragma unroll
        for (int nt = 0; nt < 4; nt++)
#pragma unroll
            for (int j = 0; j < 4; j++) acc[mt][nt][j] = 0.0f;

    for (int k0 = kbeg; k0 < kend; k0 += 32) {
        // stage A (transpose to [k][m])
        {
            const float* ap = A + (size_t)(row0 + sm) * K + k0 + skb;
#pragma unroll
            for (int c = 0; c < 4; c++) {
                float4 v = *(const float4*)(ap + c * 4);
                As[skb + c * 4 + 0][sm] = f2tf(v.x);
                As[skb + c * 4 + 1][sm] = f2tf(v.y);
                As[skb + c * 4 + 2][sm] = f2tf(v.z);
                As[skb + c * 4 + 3][sm] = f2tf(v.w);
            }
        }
        // stage B ([n][k])
        {
            const float* bp = B + (size_t)(col0 + sn) * K + k0 + skb2;
#pragma unroll
            for (int c = 0; c < 2; c++) {
                float4 v = *(const float4*)(bp + c * 4);
                Bs[sn][skb2 + c * 4 + 0] = f2tf(v.x);
                Bs[sn][skb2 + c * 4 + 1] = f2tf(v.y);
                Bs[sn][skb2 + c * 4 + 2] = f2tf(v.z);
                Bs[sn][skb2 + c * 4 + 3] = f2tf(v.w);
            }
        }
        __syncthreads();

#pragma unroll
        for (int ks = 0; ks < 4; ks++) {
            u32 af[2][4];
#pragma unroll
            for (int mt = 0; mt < 2; mt++) {
                int rb = warp_m * 32 + mt * 16;
                af[mt][0] = As[ks * 8 + t][rb + g];
                af[mt][1] = As[ks * 8 + t][rb + g + 8];
                af[mt][2] = As[ks * 8 + t + 4][rb + g];
                af[mt][3] = As[ks * 8 + t + 4][rb + g + 8];
            }
#pragma unroll
            for (int nt = 0; nt < 4; nt++) {
                int nb = warp_n * 32 + nt * 8;
                u32 b0 = Bs[nb + g][ks * 8 + t];
                u32 b1 = Bs[nb + g][ks * 8 + t + 4];
#pragma unroll
                for (int mt = 0; mt < 2; mt++)
                    mma_tf32(acc[mt][nt][0], acc[mt][nt][1], acc[mt][nt][2], acc[mt][nt][3],
                             af[mt][0], af[mt][1], af[mt][2], af[mt][3], b0, b1);
            }
        }
        __syncthreads();
    }

    // epilogue
#pragma unroll
    for (int mt = 0; mt < 2; mt++) {
        int r0 = row0 + warp_m * 32 + mt * 16 + g;
#pragma unroll
        for (int nt = 0; nt < 4; nt++) {
            int c0i = col0 + warp_n * 32 + nt * 8 + 2 * t;
            float b0 = 0.f, b1 = 0.f;
            if (bias) { b0 = bias[c0i]; b1 = bias[c0i + 1]; }
            float v0 = acc[mt][nt][0] + b0, v1 = acc[mt][nt][1] + b1;
            float v2 = acc[mt][nt][2] + b0, v3 = acc[mt][nt][3] + b1;
            if (relu) {
                v0 = fmaxf(v0, 0.f); v1 = fmaxf(v1, 0.f);
                v2 = fmaxf(v2, 0.f); v3 = fmaxf(v3, 0.f);
            }
            *(float2*)&C[(size_t)r0 * Nc + c0i] = make_float2(v0, v1);
            *(float2*)&C[(size_t)(r0 + 8) * Nc + c0i] = make_float2(v2, v3);
        }
    }
}

// ======================================================================
// Flash attention with tf32 mma: block = 64 queries x 1 head, 128 threads
// (4 warps, each warp one m16 tile of queries). Key tiles of 64.
// ======================================================================
__global__ void __launch_bounds__(128) attn_tc(const float* __restrict__ qkv,
                                               float* __restrict__ ctx)
{
    __shared__ u32 sQ[64][36];
    __shared__ u32 sK[64][36];
    __shared__ u32 sV[64][36];
    __shared__ u32 sP[64][68];

    const int h = blockIdx.y;
    const int q0 = blockIdx.x * 64;
    const int tid = threadIdx.x;
    const int wid = tid >> 5, lane = tid & 31;
    const int g = lane >> 2, t = lane & 3;
    const float SCALE = 0.17677669529663687f;   // 1/sqrt(32)

    const int qoff = h * 32;
    const int koff = DD + h * 32;
    const int voff = 2 * DD + h * 32;

    // stage Q tile (64 x 32)
    for (int r = 0; r < 4; r++) {
        int idx = r * 128 + tid;              // 0..511
        int row = idx >> 3, c = (idx & 7) * 4;
        float4 v = *(const float4*)&qkv[(size_t)(q0 + row) * 384 + qoff + c];
        sQ[row][c + 0] = f2tf(v.x); sQ[row][c + 1] = f2tf(v.y);
        sQ[row][c + 2] = f2tf(v.z); sQ[row][c + 3] = f2tf(v.w);
    }
    __syncthreads();

    // per-warp Q fragments (rows 16*wid .. +15)
    u32 qf[4][4];
    {
        int rb = wid * 16;
#pragma unroll
        for (int ks = 0; ks < 4; ks++) {
            qf[ks][0] = sQ[rb + g][ks * 8 + t];
            qf[ks][1] = sQ[rb + g + 8][ks * 8 + t];
            qf[ks][2] = sQ[rb + g][ks * 8 + t + 4];
            qf[ks][3] = sQ[rb + g + 8][ks * 8 + t + 4];
        }
    }

    float O[4][4];
#pragma unroll
    for (int nt = 0; nt < 4; nt++)
#pragma unroll
        for (int j = 0; j < 4; j++) O[nt][j] = 0.0f;
    float m_g = -CUDART_INF_F, m_g8 = -CUDART_INF_F;
    float lg = 0.0f, lg8 = 0.0f;

    for (int kt = 0; kt < NN / 64; kt++) {
        __syncthreads();   // previous tile's PV done before overwrite
        // stage K,V tile (64 keys x 32)
        for (int r = 0; r < 4; r++) {
            int idx = r * 128 + tid;
            int row = idx >> 3, c = (idx & 7) * 4;
            const float* base = &qkv[(size_t)(kt * 64 + row) * 384];
            float4 kv = *(const float4*)(base + koff + c);
            sK[row][c + 0] = f2tf(kv.x); sK[row][c + 1] = f2tf(kv.y);
            sK[row][c + 2] = f2tf(kv.z); sK[row][c + 3] = f2tf(kv.w);
            float4 vv = *(const float4*)(base + voff + c);
            sV[row][c + 0] = f2tf(vv.x); sV[row][c + 1] = f2tf(vv.y);
            sV[row][c + 2] = f2tf(vv.z); sV[row][c + 3] = f2tf(vv.w);
        }
        __syncthreads();

        // S = Q K^T (16 x 64 per warp)
        float sc[8][4];
#pragma unroll
        for (int nt = 0; nt < 8; nt++)
#pragma unroll
            for (int j = 0; j < 4; j++) sc[nt][j] = 0.0f;
#pragma unroll
        for (int ks = 0; ks < 4; ks++) {
#pragma unroll
            for (int nt = 0; nt < 8; nt++) {
                u32 b0 = sK[nt * 8 + g][ks * 8 + t];
                u32 b1 = sK[nt * 8 + g][ks * 8 + t + 4];
                mma_tf32(sc[nt][0], sc[nt][1], sc[nt][2], sc[nt][3],
                         qf[ks][0], qf[ks][1], qf[ks][2], qf[ks][3], b0, b1);
            }
        }

        // scaled row maxima (rows g and g+8)
        float rg = -CUDART_INF_F, rg8 = -CUDART_INF_F;
#pragma unroll
        for (int nt = 0; nt < 8; nt++) {
            sc[nt][0] *= SCALE; sc[nt][1] *= SCALE;
            sc[nt][2] *= SCALE; sc[nt][3] *= SCALE;
            rg  = fmaxf(rg,  fmaxf(sc[nt][0], sc[nt][1]));
            rg8 = fmaxf(rg8, fmaxf(sc[nt][2], sc[nt][3]));
        }
        rg  = fmaxf(rg,  __shfl_xor_sync(0xffffffffu, rg, 1));
        rg  = fmaxf(rg,  __shfl_xor_sync(0xffffffffu, rg, 2));
        rg8 = fmaxf(rg8, __shfl_xor_sync(0xffffffffu, rg8, 1));
        rg8 = fmaxf(rg8, __shfl_xor_sync(0xffffffffu, rg8, 2));

        float mng = fmaxf(m_g, rg),  fg  = __expf(m_g - mng);
        float mng8 = fmaxf(m_g8, rg8), fg8 = __expf(m_g8 - mng8);
        m_g = mng; m_g8 = mng8;
        lg *= fg; lg8 *= fg8;
#pragma unroll
        for (int nt = 0; nt < 4; nt++) {
            O[nt][0] *= fg;  O[nt][1] *= fg;
            O[nt][2] *= fg8; O[nt][3] *= fg8;
        }

        // P = exp(S - m), store to sP (tf32)
        int rb = wid * 16;
#pragma unroll
        for (int nt = 0; nt < 8; nt++) {
            float p0 = __expf(sc[nt][0] - m_g);
            float p1 = __expf(sc[nt][1] - m_g);
            float p2 = __expf(sc[nt][2] - m_g8);
            float p3 = __expf(sc[nt][3] - m_g8);
            lg += p0 + p1; lg8 += p2 + p3;
            int cc = nt * 8 + 2 * t;
            sP[rb + g][cc] = f2tf(p0);     sP[rb + g][cc + 1] = f2tf(p1);
            sP[rb + g + 8][cc] = f2tf(p2); sP[rb + g + 8][cc + 1] = f2tf(p3);
        }
        __syncwarp();

        // O += P V  (m=16 q, n=32 dh, k=64 keys)
#pragma unroll
        for (int ks = 0; ks < 8; ks++) {
            u32 a0 = sP[rb + g][ks * 8 + t];
            u32 a1 = sP[rb + g + 8][ks * 8 + t];
            u32 a2 = sP[rb + g][ks * 8 + t + 4];
            u32 a3 = sP[rb + g + 8][ks * 8 + t + 4];
#pragma unroll
            for (int nt = 0; nt < 4; nt++) {
                u32 b0 = sV[ks * 8 + t][nt * 8 + g];
                u32 b1 = sV[ks * 8 + t + 4][nt * 8 + g];
                mma_tf32(O[nt][0], O[nt][1], O[nt][2], O[nt][3],
                         a0, a1, a2, a3, b0, b1);
            }
        }
    }

    // finalize: reduce l across quad, normalize, write
    lg  += __shfl_xor_sync(0xffffffffu, lg, 1);
    lg  += __shfl_xor_sync(0xffffffffu, lg, 2);
    lg8 += __shfl_xor_sync(0xffffffffu, lg8, 1);
    lg8 += __shfl_xor_sync(0xffffffffu, lg8, 2);
    float ig = 1.0f / lg, ig8 = 1.0f / lg8;
    int r0 = q0 + wid * 16 + g;
#pragma unroll
    for (int nt = 0; nt < 4; nt++) {
        int cc = h * 32 + nt * 8 + 2 * t;
        *(float2*)&ctx[(size_t)r0 * DD + cc] = make_float2(O[nt][0] * ig, O[nt][1] * ig);
        *(float2*)&ctx[(size_t)(r0 + 8) * DD + cc] = make_float2(O[nt][2] * ig8, O[nt][3] * ig8);
    }
}

// ======================================================================
// FFMA2 SGEMM (kept for GCN layers): C = A[M,K]*B[Nc,K]^T
// ======================================================================
__global__ void __launch_bounds__(256) gemm2_kernel(
    const float* __restrict__ A, const float* __restrict__ B,
    const float* __restrict__ bias, float* __restrict__ C,
    int M, int Nc, int K, int relu, int kslice)
{
    __shared__ float As[16][128];
    __shared__ float Bs[16][64];
    const int tid = threadIdx.x;
    const int row0 = blockIdx.y * 128, col0 = blockIdx.x * 64;
    const int kbeg = blockIdx.z * kslice, kend = kbeg + kslice;
    C += (size_t)blockIdx.z * M * Nc;

    const int lrA = tid >> 1, lkA = (tid & 1) * 8;
    const int lrB = tid >> 2, lkB = (tid & 3) * 4;
    const int tx = tid & 15, ty = tid >> 4;

    const unsigned aBase = smem_u32(As) + ty * 32;
    ull acc[4][4] = {};

    for (int k0 = kbeg; k0 < kend; k0 += 16) {
        const float* ap = A + (size_t)(row0 + lrA) * K + k0 + lkA;
        float4 a0 = *(const float4*)ap;
        float4 a1 = *(const float4*)(ap + 4);
        As[lkA + 0][lrA] = a0.x; As[lkA + 1][lrA] = a0.y;
        As[lkA + 2][lrA] = a0.z; As[lkA + 3][lrA] = a0.w;
        As[lkA + 4][lrA] = a1.x; As[lkA + 5][lrA] = a1.y;
        As[lkA + 6][lrA] = a1.z; As[lkA + 7][lrA] = a1.w;
        float4 b = *(const float4*)(B + (size_t)(col0 + lrB) * K + k0 + lkB);
        Bs[lkB + 0][lrB] = b.x; Bs[lkB + 1][lrB] = b.y;
        Bs[lkB + 2][lrB] = b.z; Bs[lkB + 3][lrB] = b.w;
        __syncthreads();
#pragma unroll
        for (int k = 0; k < 16; k++) {
            ull a01, a23, a45, a67;
            lds2(a01, a23, aBase + k * 512);
            lds2(a45, a67, aBase + k * 512 + 16);
            float4 bv = *(const float4*)&Bs[k][tx * 4];
            ull b0 = dup2(bv.x), b1 = dup2(bv.y), b2 = dup2(bv.z), b3 = dup2(bv.w);
            acc[0][0] = ffma2(a01, b0, acc[0][0]);
            acc[0][1] = ffma2(a01, b1, acc[0][1]);
            acc[0][2] = ffma2(a01, b2, acc[0][2]);
            acc[0][3] = ffma2(a01, b3, acc[0][3]);
            acc[1][0] = ffma2(a23, b0, acc[1][0]);
            acc[1][1] = ffma2(a23, b1, acc[1][1]);
            acc[1][2] = ffma2(a23, b2, acc[1][2]);
            acc[1][3] = ffma2(a23, b3, acc[1][3]);
            acc[2][0] = ffma2(a45, b0, acc[2][0]);
            acc[2][1] = ffma2(a45, b1, acc[2][1]);
            acc[2][2] = ffma2(a45, b2, acc[2][2]);
            acc[2][3] = ffma2(a45, b3, acc[2][3]);
            acc[3][0] = ffma2(a67, b0, acc[3][0]);
            acc[3][1] = ffma2(a67, b1, acc[3][1]);
            acc[3][2] = ffma2(a67, b2, acc[3][2]);
            acc[3][3] = ffma2(a67, b3, acc[3][3]);
        }
        __syncthreads();
    }

    float4 bb = make_float4(0.f, 0.f, 0.f, 0.f);
    if (bias) bb = *(const float4*)&bias[col0 + tx * 4];
#pragma unroll
    for (int ip = 0; ip < 4; ip++) {
        float lo0, hi0, lo1, hi1, lo2, hi2, lo3, hi3;
        unpack2(acc[ip][0], lo0, hi0);
        unpack2(acc[ip][1], lo1, hi1);
        unpack2(acc[ip][2], lo2, hi2);
        unpack2(acc[ip][3], lo3, hi3);
        float4 e = make_float4(lo0 + bb.x, lo1 + bb.y, lo2 + bb.z, lo3 + bb.w);
        float4 o = make_float4(hi0 + bb.x, hi1 + bb.y, hi2 + bb.z, hi3 + bb.w);
        if (relu) {
            e.x = fmaxf(e.x, 0.f); e.y = fmaxf(e.y, 0.f);
            e.z = fmaxf(e.z, 0.f); e.w = fmaxf(e.w, 0.f);
            o.x = fmaxf(o.x, 0.f); o.y = fmaxf(o.y, 0.f);
            o.z = fmaxf(o.z, 0.f); o.w = fmaxf(o.w, 0.f);
        }
        int r = row0 + ty * 8 + ip * 2;
        *(float4*)&C[(size_t)r * Nc + col0 + tx * 4] = e;
        *(float4*)&C[(size_t)(r + 1) * Nc + col0 + tx * 4] = o;
    }
}

// ---------------- residual + LayerNorm -------------------------------------
__global__ void ln_kernel(const float* __restrict__ x, const float* __restrict__ r,
                          const float* __restrict__ g, const float* __restrict__ b,
                          float* __restrict__ out)
{
    int n = blockIdx.x, t = threadIdx.x;
    int lane = t & 31, w = t >> 5;
    float v = x[(size_t)n * DD + t] + r[(size_t)n * DD + t];

    __shared__ float red[8];
    float s = v;
#pragma unroll
    for (int off = 16; off > 0; off >>= 1) s += __shfl_xor_sync(0xffffffffu, s, off);
    if (lane == 0) red[w] = s;
    __syncthreads();
    float mu = (red[0] + red[1] + red[2] + red[3]) * (1.0f / DD);

    float d = v - mu;
    float sq = d * d;
#pragma unroll
    for (int off = 16; off > 0; off >>= 1) sq += __shfl_xor_sync(0xffffffffu, sq, off);
    if (lane == 0) red[4 + w] = sq;
    __syncthreads();
    float var = (red[4] + red[5] + red[6] + red[7]) * (1.0f / DD);

    out[(size_t)n * DD + t] = d * rsqrtf(var + LNEPS) * g[t] + b[t];
}

__global__ void ln_sum4_kernel(const float* __restrict__ x,
                               const float* __restrict__ parts,
                               const float* __restrict__ fb,
                               const float* __restrict__ g,
                               const float* __restrict__ b,
                               float* __restrict__ out)
{
    int n = blockIdx.x, t = threadIdx.x;
    int lane = t & 31, w = t >> 5;
    size_t i = (size_t)n * DD + t;
    const size_t ps = (size_t)NN * DD;
    float v = x[i] + fb[t] + parts[i] + parts[i + ps] + parts[i + 2 * ps] + parts[i + 3 * ps];

    __shared__ float red[8];
    float s = v;
#pragma unroll
    for (int off = 16; off > 0; off >>= 1) s += __shfl_xor_sync(0xffffffffu, s, off);
    if (lane == 0) red[w] = s;
    __syncthreads();
    float mu = (red[0] + red[1] + red[2] + red[3]) * (1.0f / DD);

    float d = v - mu;
    float sq = d * d;
#pragma unroll
    for (int off = 16; off > 0; off >>= 1) sq += __shfl_xor_sync(0xffffffffu, sq, off);
    if (lane == 0) red[4 + w] = sq;
    __syncthreads();
    float var = (red[4] + red[5] + red[6] + red[7]) * (1.0f / DD);

    out[i] = d * rsqrtf(var + LNEPS) * g[t] + b[t];
}

// ---------------- GCN graph preprocessing ---------------------------------
__global__ void zero_cnt_kernel() {
    int i = blockIdx.x * blockDim.x + threadIdx.x;
    if (i < NN) g_cnt[i] = 0;
}
__global__ void count_kernel(const int* __restrict__ dst) {
    int e = blockIdx.x * blockDim.x + threadIdx.x;
    if (e < EE) atomicAdd(&g_cnt[dst[e]], 1);
}
__global__ void dinv_kernel() {
    int i = blockIdx.x * blockDim.x + threadIdx.x;
    if (i < NN) g_dinv[i] = rsqrtf((float)g_cnt[i] + 1.0f);
}
__global__ void scan_kernel() {
    __shared__ int sh[1024];
    int t = threadIdx.x;
    int base = t * 4;
    int c0 = g_cnt[base + 0], c1 = g_cnt[base + 1];
    int c2 = g_cnt[base + 2], c3 = g_cnt[base + 3];
    int local = c0 + c1 + c2 + c3;
    sh[t] = local;
    __syncthreads();
    for (int off = 1; off < 1024; off <<= 1) {
        int v = (t >= off) ? sh[t - off] : 0;
        __syncthreads();
        sh[t] += v;
        __syncthreads();
    }
    int excl = sh[t] - local;
    int p0 = excl, p1 = excl + c0, p2 = p1 + c1, p3 = p2 + c2;
    g_rowptr[base + 0] = p0; g_rowptr[base + 1] = p1;
    g_rowptr[base + 2] = p2; g_rowptr[base + 3] = p3;
    g_fillpos[base + 0] = p0; g_fillpos[base + 1] = p1;
    g_fillpos[base + 2] = p2; g_fillpos[base + 3] = p3;
    if (t == 1023) g_rowptr[NN] = excl + local;
}
__global__ void fill_kernel(const int* __restrict__ src, const int* __restrict__ dst) {
    int e = blockIdx.x * blockDim.x + threadIdx.x;
    if (e < EE) {
        int d = dst[e];
        int pos = atomicAdd(&g_fillpos[d], 1);
        g_col[pos] = src[e];
    }
}

// ---------------- GCN aggregation: gather over CSR -------------------------
template<int F, bool RELU>
__global__ void gather_kernel(const float* __restrict__ hw,
                              const float* __restrict__ bias,
                              float* __restrict__ out)
{
    constexpr int TPR = F / 4;
    constexpr int RPB = 256 / TPR;
    int tid = threadIdx.x;
    int r = blockIdx.x * RPB + tid / TPR;
    int lane = tid % TPR;
    const float4* hw4 = (const float4*)hw;

    float dr = g_dinv[r];
    float4 acc = hw4[(size_t)r * TPR + lane];
    float self = dr * dr;
    acc.x *= self; acc.y *= self; acc.z *= self; acc.w *= self;

    int p1 = g_rowptr[r + 1];
    for (int p = g_rowptr[r]; p < p1; p++) {
        int s = g_col[p];
        float nrm = g_dinv[s] * dr;
        float4 hv = hw4[(size_t)s * TPR + lane];
        acc.x += nrm * hv.x; acc.y += nrm * hv.y;
        acc.z += nrm * hv.z; acc.w += nrm * hv.w;
    }
    float4 bb = *(const float4*)&bias[lane * 4];
    acc.x += bb.x; acc.y += bb.y; acc.z += bb.z; acc.w += bb.w;
    if (RELU) {
        acc.x = fmaxf(acc.x, 0.f); acc.y = fmaxf(acc.y, 0.f);
        acc.z = fmaxf(acc.z, 0.f); acc.w = fmaxf(acc.w, 0.f);
    }
    *(float4*)&out[(size_t)r * F + lane * 4] = acc;
}

// ---------------- launch ---------------------------------------------------
extern "C" void kernel_launch(void* const* d_in, const int* in_sizes, int n_in,
                              void* d_out, int out_size)
{
    const float* x          = (const float*)d_in[0];
    const int*   edge_index = (const int*)  d_in[1];
    const float* in_proj_w  = (const float*)d_in[2];
    const float* in_proj_b  = (const float*)d_in[3];
    const float* out_proj_w = (const float*)d_in[4];
    const float* out_proj_b = (const float*)d_in[5];
    const float* ln1_g      = (const float*)d_in[6];
    const float* ln1_b      = (const float*)d_in[7];
    const float* ffn_w1     = (const float*)d_in[8];
    const float* ffn_b1     = (const float*)d_in[9];
    const float* ffn_w2     = (const float*)d_in[10];
    const float* ffn_b2     = (const float*)d_in[11];
    const float* ln2_g      = (const float*)d_in[12];
    const float* ln2_b      = (const float*)d_in[13];
    const float* gcn1_w     = (const float*)d_in[14];
    const float* gcn1_b     = (const float*)d_in[15];
    const float* gcn2_w     = (const float*)d_in[16];
    const float* gcn2_b     = (const float*)d_in[17];
    const float* gcn3_w     = (const float*)d_in[18];
    const float* gcn3_b     = (const float*)d_in[19];
    float* out = (float*)d_out;

    const int* src = edge_index;
    const int* dst = edge_index + EE;

    float *p_qkv, *p_ctx, *p_tmp, *p_y, *p_mid, *p_z, *p_f2, *p_hw, *p_h1, *p_h2;
    cudaGetSymbolAddress((void**)&p_qkv,  g_qkv);
    cudaGetSymbolAddress((void**)&p_ctx,  g_ctx);
    cudaGetSymbolAddress((void**)&p_tmp,  g_tmp);
    cudaGetSymbolAddress((void**)&p_y,    g_y);
    cudaGetSymbolAddress((void**)&p_mid,  g_mid);
    cudaGetSymbolAddress((void**)&p_z,    g_z);
    cudaGetSymbolAddress((void**)&p_f2,   g_f2);
    cudaGetSymbolAddress((void**)&p_hw,   g_hw);
    cudaGetSymbolAddress((void**)&p_h1,   g_h1);
    cudaGetSymbolAddress((void**)&p_h2,   g_h2);

    // ---- transformer encoder layer (tf32 tensor cores) ----
    gemm_tc<<<dim3(384 / 64, NN / 128), 256>>>(x, in_proj_w, in_proj_b, p_qkv,
                                               NN, 384, DD, 0, DD);
    attn_tc<<<dim3(NN / 64, HH), 128>>>(p_qkv, p_ctx);
    gemm_tc<<<dim3(DD / 64, NN / 128), 256>>>(p_ctx, out_proj_w, out_proj_b, p_tmp,
                                              NN, DD, DD, 0, DD);
    ln_kernel<<<NN, DD>>>(x, p_tmp, ln1_g, ln1_b, p_y);
    gemm_tc<<<dim3(DFF / 64, NN / 128), 256>>>(p_y, ffn_w1, ffn_b1, p_mid,
                                               NN, DFF, DD, 1, DD);
    gemm_tc<<<dim3(DD / 64, NN / 128, FSPLIT), 256>>>(p_mid, ffn_w2, nullptr, p_f2,
                                                      NN, DD, DFF, 0, DFF / FSPLIT);
    ln_sum4_kernel<<<NN, DD>>>(p_y, p_f2, ffn_b2, ln2_g, ln2_b, p_z);

    // ---- graph preprocessing (CSR by dst) ----
    zero_cnt_kernel<<<NN / 256, 256>>>();
    count_kernel<<<EE / 256, 256>>>(dst);
    dinv_kernel<<<NN / 256, 256>>>();
    scan_kernel<<<1, 1024>>>();
    fill_kernel<<<EE / 256, 256>>>(src, dst);

    // ---- GCN layers (fp32 FFMA2 gemms + CSR gathers) ----
    gemm2_kernel<<<dim3(HID / 64, NN / 128), 256>>>(p_z, gcn1_w, nullptr, p_hw,
                                                    NN, HID, DD, 0, DD);
    gather_kernel<HID, true><<<NN / 4, 256>>>(p_hw, gcn1_b, p_h1);

    gemm2_kernel<<<dim3(HID / 64, NN / 128), 256>>>(p_h1, gcn2_w, nullptr, p_hw,
                                                    NN, HID, HID, 0, HID);
    gather_kernel<HID, true><<<NN / 4, 256>>>(p_hw, gcn2_b, p_h2);

    gemm2_kernel<<<dim3(OUTD / 64, NN / 128), 256>>>(p_h2, gcn3_w, nullptr, p_hw,
                                                     NN, OUTD, HID, 0, HID);
    gather_kernel<OUTD, false><<<NN / 16, 256>>>(p_hw, gcn3_b, out);
}

// round 5
// speedup vs baseline: 4.0730x; 1.4544x over previous
#include <cuda_runtime.h>
#include <cuda_bf16.h>
#include <math_constants.h>

// ---------------- problem constants ----------------
#define NN   4096
#define DD   128
#define HH   4
#define DHH  32
#define DFF  2048
#define HID  256
#define OUTD 64
#define EE   131072
#define LNEPS 1e-5f
#define FSPLIT 4

typedef unsigned u32;

// ---------------- helpers ----------------
__device__ __forceinline__ unsigned smem_u32(const void* p) {
    unsigned a;
    asm("{ .reg .u64 t; cvta.to.shared.u64 t, %1; cvt.u32.u64 %0, t; }"
        : "=r"(a) : "l"(p));
    return a;
}
__device__ __forceinline__ void cp16(u32 saddr, const void* gptr) {
    asm volatile("cp.async.ca.shared.global [%0], [%1], 16;"
                 :: "r"(saddr), "l"(gptr) : "memory");
}
__device__ __forceinline__ void cpcommit() {
    asm volatile("cp.async.commit_group;" ::: "memory");
}
__device__ __forceinline__ void cpwait0() {
    asm volatile("cp.async.wait_group 0;" ::: "memory");
}
__device__ __forceinline__ void cpwait1() {
    asm volatile("cp.async.wait_group 1;" ::: "memory");
}
// round-to-nearest tf32 conversion (the one that keeps error unbiased)
__device__ __forceinline__ u32 f2tf(float x) {
    u32 u; asm("cvt.rna.tf32.f32 %0, %1;" : "=r"(u) : "f"(x));
    return u;
}
__device__ __forceinline__ void mma_tf32(float& d0, float& d1, float& d2, float& d3,
                                         u32 a0, u32 a1, u32 a2, u32 a3,
                                         u32 b0, u32 b1) {
    asm volatile(
        "mma.sync.aligned.m16n8k8.row.col.f32.tf32.tf32.f32 "
        "{%0,%1,%2,%3}, {%4,%5,%6,%7}, {%8,%9}, {%0,%1,%2,%3};\n"
        : "+f"(d0), "+f"(d1), "+f"(d2), "+f"(d3)
        : "r"(a0), "r"(a1), "r"(a2), "r"(a3), "r"(b0), "r"(b1));
}

// ---------------- scratch ----------------
__device__ float g_qkv[NN * 384];
__device__ float g_ctx[NN * DD];
__device__ float g_tmp[NN * DD];     // attn_out; later reused as GCN agg buffer
__device__ float g_y[NN * DD];
__device__ float g_mid[NN * DFF];
__device__ float g_z[NN * DD];
__device__ float g_f2[FSPLIT * NN * DD];
__device__ float g_hw[NN * HID];
__device__ float g_h1[NN * HID];
__device__ float g_h2[NN * HID];
__device__ float g_dinv[NN];
__device__ int   g_cnt[NN];
__device__ int   g_rowptr[NN + 1];
__device__ int   g_fillpos[NN];
__device__ int   g_col[EE];

// ======================================================================
// tf32 tensor-core GEMM with cp.async double buffering.
// C = A[M,K]*B[Nc,K]^T (+bias)(+relu). Block tile BM x 64, BK=32.
// BM=128: 256 thr (8 warps 4x2). BM=64: 128 thr (4 warps 2x2).
// Fragments RN-converted to tf32 at register load.
// Optional K-split via blockIdx.z (kslice); slice z writes C + z*M*Nc.
// ======================================================================
#define STR 44   // smem row stride in floats (16B-aligned, conflict-free frags)

template<int BM>
__global__ void __launch_bounds__(BM * 2) gemm_tc(
    const float* __restrict__ A, const float* __restrict__ B,
    const float* __restrict__ bias, float* __restrict__ C,
    int M, int Nc, int K, int relu, int kslice)
{
    extern __shared__ float smem[];
    float* As = smem;                  // [2][BM][STR]
    float* Bs = smem + 2 * BM * STR;   // [2][64][STR]
    const int THREADS = BM * 2;

    const int tid = threadIdx.x;
    const int wid = tid >> 5, lane = tid & 31;
    const int g = lane >> 2, t = lane & 3;
    const int warp_m = wid >> 1, warp_n = wid & 1;
    const int row0 = blockIdx.y * BM, col0 = blockIdx.x * 64;
    const int kbeg = blockIdx.z * kslice;
    const int niter = kslice / 32;
    C += (size_t)blockIdx.z * M * Nc;

    const u32 sAa = smem_u32(As), sBa = smem_u32(Bs);

    float acc[2][4][4];
#pragma unroll
    for (int mt = 0; mt < 2; mt++)
#pragma unroll
        for (int nt = 0; nt < 4; nt++)
#pragma unroll
            for (int j = 0; j < 4; j++) acc[mt][nt][j] = 0.0f;

    auto issue = [&](int it, int buf) {
        const float* abase = A + (size_t)row0 * K + kbeg + it * 32;
        u32 ad = sAa + buf * BM * STR * 4;
#pragma unroll
        for (int i = 0; i < 4; i++) {
            int c = tid + i * THREADS;          // BM*8 chunks
            int rr = c >> 3, kc = (c & 7) * 4;
            cp16(ad + (rr * STR + kc) * 4, abase + (size_t)rr * K + kc);
        }
        const float* bbase = B + (size_t)col0 * K + kbeg + it * 32;
        u32 bd = sBa + buf * 64 * STR * 4;
#pragma unroll
        for (int i = 0; i < 512 / (BM * 2); i++) {
            int c = tid + i * THREADS;          // 512 chunks
            int rr = c >> 3, kc = (c & 7) * 4;
            cp16(bd + (rr * STR + kc) * 4, bbase + (size_t)rr * K + kc);
        }
        cpcommit();
    };

    issue(0, 0);
    for (int it = 0; it < niter; it++) {
        if (it + 1 < niter) issue(it + 1, (it + 1) & 1);
        if (it + 1 < niter) cpwait1(); else cpwait0();
        __syncthreads();

        const float* Ab = As + (it & 1) * BM * STR;
        const float* Bb = Bs + (it & 1) * 64 * STR;
#pragma unroll
        for (int ks = 0; ks < 4; ks++) {
            u32 af[2][4];
#pragma unroll
            for (int mt = 0; mt < 2; mt++) {
                int rb = warp_m * 32 + mt * 16;
                af[mt][0] = f2tf(Ab[(rb + g) * STR + ks * 8 + t]);
                af[mt][1] = f2tf(Ab[(rb + g + 8) * STR + ks * 8 + t]);
                af[mt][2] = f2tf(Ab[(rb + g) * STR + ks * 8 + t + 4]);
                af[mt][3] = f2tf(Ab[(rb + g + 8) * STR + ks * 8 + t + 4]);
            }
#pragma unroll
            for (int nt = 0; nt < 4; nt++) {
                int nb = warp_n * 32 + nt * 8;
                u32 b0 = f2tf(Bb[(nb + g) * STR + ks * 8 + t]);
                u32 b1 = f2tf(Bb[(nb + g) * STR + ks * 8 + t + 4]);
#pragma unroll
                for (int mt = 0; mt < 2; mt++)
                    mma_tf32(acc[mt][nt][0], acc[mt][nt][1], acc[mt][nt][2], acc[mt][nt][3],
                             af[mt][0], af[mt][1], af[mt][2], af[mt][3], b0, b1);
            }
        }
        __syncthreads();
    }

#pragma unroll
    for (int mt = 0; mt < 2; mt++) {
        int r0 = row0 + warp_m * 32 + mt * 16 + g;
#pragma unroll
        for (int nt = 0; nt < 4; nt++) {
            int c0i = col0 + warp_n * 32 + nt * 8 + 2 * t;
            float b0 = 0.f, b1 = 0.f;
            if (bias) { b0 = bias[c0i]; b1 = bias[c0i + 1]; }
            float v0 = acc[mt][nt][0] + b0, v1 = acc[mt][nt][1] + b1;
            float v2 = acc[mt][nt][2] + b0, v3 = acc[mt][nt][3] + b1;
            if (relu) {
                v0 = fmaxf(v0, 0.f); v1 = fmaxf(v1, 0.f);
                v2 = fmaxf(v2, 0.f); v3 = fmaxf(v3, 0.f);
            }
            *(float2*)&C[(size_t)r0 * Nc + c0i] = make_float2(v0, v1);
            *(float2*)&C[(size_t)(r0 + 8) * Nc + c0i] = make_float2(v2, v3);
        }
    }
}

// ======================================================================
// Flash attention, tf32 mma, cp.async double-buffered K/V.
// Block = 64 queries x 1 head, 128 threads (4 warps x m16 query tile).
// ======================================================================
__global__ void __launch_bounds__(128) attn_tc(const float* __restrict__ qkv,
                                               float* __restrict__ ctx)
{
    extern __shared__ float smem[];
    float* sK = smem;                   // [2][64][STR]
    float* sV = smem + 2 * 64 * STR;    // [2][64][STR]
    float* sQ = smem + 4 * 64 * STR;    // [64][STR], reused as sP [64][68]
    u32*   sP = (u32*)sQ;

    const int h = blockIdx.y;
    const int q0 = blockIdx.x * 64;
    const int tid = threadIdx.x;
    const int wid = tid >> 5, lane = tid & 31;
    const int g = lane >> 2, t = lane & 3;
    const int rb = wid * 16;
    const float SCALE = 0.17677669529663687f;   // 1/sqrt(32)

    const int qoff = h * 32;
    const int koff = DD + h * 32;
    const int voff = 2 * DD + h * 32;

    const u32 sKa = smem_u32(sK), sVa = smem_u32(sV), sQa = smem_u32(sQ);

    // stage Q (group 0)
#pragma unroll
    for (int i = 0; i < 4; i++) {
        int c = tid + i * 128;
        int rr = c >> 3, kc = (c & 7) * 4;
        cp16(sQa + (rr * STR + kc) * 4, &qkv[(size_t)(q0 + rr) * 384 + qoff + kc]);
    }
    cpcommit();

    auto issueKV = [&](int kt, int buf) {
#pragma unroll
        for (int i = 0; i < 4; i++) {
            int c = tid + i * 128;
            int rr = c >> 3, kc = (c & 7) * 4;
            const float* base = &qkv[(size_t)(kt * 64 + rr) * 384];
            cp16(sKa + (buf * 64 * STR + rr * STR + kc) * 4, base + koff + kc);
            cp16(sVa + (buf * 64 * STR + rr * STR + kc) * 4, base + voff + kc);
        }
        cpcommit();
    };

    issueKV(0, 0);
    cpwait1();              // Q group done (KV0 may be in flight)
    __syncthreads();

    // Q fragments, pre-scaled by 1/sqrt(dh), RN tf32
    u32 qf[4][4];
#pragma unroll
    for (int ks = 0; ks < 4; ks++) {
        qf[ks][0] = f2tf(sQ[(rb + g) * STR + ks * 8 + t] * SCALE);
        qf[ks][1] = f2tf(sQ[(rb + g + 8) * STR + ks * 8 + t] * SCALE);
        qf[ks][2] = f2tf(sQ[(rb + g) * STR + ks * 8 + t + 4] * SCALE);
        qf[ks][3] = f2tf(sQ[(rb + g + 8) * STR + ks * 8 + t + 4] * SCALE);
    }

    float O[4][4];
#pragma unroll
    for (int nt = 0; nt < 4; nt++)
#pragma unroll
        for (int j = 0; j < 4; j++) O[nt][j] = 0.0f;
    float m_g = -CUDART_INF_F, m_g8 = -CUDART_INF_F;
    float lg = 0.0f, lg8 = 0.0f;

    for (int kt = 0; kt < NN / 64; kt++) {
        if (kt + 1 < NN / 64) issueKV(kt + 1, (kt + 1) & 1);
        if (kt + 1 < NN / 64) cpwait1(); else cpwait0();
        __syncthreads();

        const float* K_ = sK + (kt & 1) * 64 * STR;
        const float* V_ = sV + (kt & 1) * 64 * STR;

        // S = Q K^T (16 x 64 per warp)
        float sc[8][4];
#pragma unroll
        for (int nt = 0; nt < 8; nt++)
#pragma unroll
            for (int j = 0; j < 4; j++) sc[nt][j] = 0.0f;
#pragma unroll
        for (int ks = 0; ks < 4; ks++) {
#pragma unroll
            for (int nt = 0; nt < 8; nt++) {
                u32 b0 = f2tf(K_[(nt * 8 + g) * STR + ks * 8 + t]);
                u32 b1 = f2tf(K_[(nt * 8 + g) * STR + ks * 8 + t + 4]);
                mma_tf32(sc[nt][0], sc[nt][1], sc[nt][2], sc[nt][3],
                         qf[ks][0], qf[ks][1], qf[ks][2], qf[ks][3], b0, b1);
            }
        }

        // row maxima (rows g and g+8)
        float rg = -CUDART_INF_F, rg8 = -CUDART_INF_F;
#pragma unroll
        for (int nt = 0; nt < 8; nt++) {
            rg  = fmaxf(rg,  fmaxf(sc[nt][0], sc[nt][1]));
            rg8 = fmaxf(rg8, fmaxf(sc[nt][2], sc[nt][3]));
        }
        rg  = fmaxf(rg,  __shfl_xor_sync(0xffffffffu, rg, 1));
        rg  = fmaxf(rg,  __shfl_xor_sync(0xffffffffu, rg, 2));
        rg8 = fmaxf(rg8, __shfl_xor_sync(0xffffffffu, rg8, 1));
        rg8 = fmaxf(rg8, __shfl_xor_sync(0xffffffffu, rg8, 2));

        float mng = fmaxf(m_g, rg),   fg  = __expf(m_g - mng);
        float mng8 = fmaxf(m_g8, rg8), fg8 = __expf(m_g8 - mng8);
        m_g = mng; m_g8 = mng8;
        lg *= fg; lg8 *= fg8;
#pragma unroll
        for (int nt = 0; nt < 4; nt++) {
            O[nt][0] *= fg;  O[nt][1] *= fg;
            O[nt][2] *= fg8; O[nt][3] *= fg8;
        }

        // P = exp(S - m) -> sP (tf32 RN)
#pragma unroll
        for (int nt = 0; nt < 8; nt++) {
            float p0 = __expf(sc[nt][0] - m_g);
            float p1 = __expf(sc[nt][1] - m_g);
            float p2 = __expf(sc[nt][2] - m_g8);
            float p3 = __expf(sc[nt][3] - m_g8);
            lg += p0 + p1; lg8 += p2 + p3;
            int cc = nt * 8 + 2 * t;
            sP[(rb + g) * 68 + cc] = f2tf(p0);     sP[(rb + g) * 68 + cc + 1] = f2tf(p1);
            sP[(rb + g + 8) * 68 + cc] = f2tf(p2); sP[(rb + g + 8) * 68 + cc + 1] = f2tf(p3);
        }
        __syncwarp();

        // O += P V
#pragma unroll
        for (int ks = 0; ks < 8; ks++) {
            u32 a0 = sP[(rb + g) * 68 + ks * 8 + t];
            u32 a1 = sP[(rb + g + 8) * 68 + ks * 8 + t];
            u32 a2 = sP[(rb + g) * 68 + ks * 8 + t + 4];
            u32 a3 = sP[(rb + g + 8) * 68 + ks * 8 + t + 4];
#pragma unroll
            for (int nt = 0; nt < 4; nt++) {
                u32 b0 = f2tf(V_[(ks * 8 + t) * STR + nt * 8 + g]);
                u32 b1 = f2tf(V_[(ks * 8 + t + 4) * STR + nt * 8 + g]);
                mma_tf32(O[nt][0], O[nt][1], O[nt][2], O[nt][3],
                         a0, a1, a2, a3, b0, b1);
            }
        }
        __syncthreads();
    }

    lg  += __shfl_xor_sync(0xffffffffu, lg, 1);
    lg  += __shfl_xor_sync(0xffffffffu, lg, 2);
    lg8 += __shfl_xor_sync(0xffffffffu, lg8, 1);
    lg8 += __shfl_xor_sync(0xffffffffu, lg8, 2);
    float ig = 1.0f / lg, ig8 = 1.0f / lg8;
    int r0 = q0 + rb + g;
#pragma unroll
    for (int nt = 0; nt < 4; nt++) {
        int cc = h * 32 + nt * 8 + 2 * t;
        *(float2*)&ctx[(size_t)r0 * DD + cc] = make_float2(O[nt][0] * ig, O[nt][1] * ig);
        *(float2*)&ctx[(size_t)(r0 + 8) * DD + cc] = make_float2(O[nt][2] * ig8, O[nt][3] * ig8);
    }
}

// ---------------- warp-per-row residual + LayerNorm ------------------------
__global__ void __launch_bounds__(256) ln_kernel(
    const float* __restrict__ x, const float* __restrict__ r,
    const float* __restrict__ g, const float* __restrict__ b,
    float* __restrict__ out)
{
    int row = blockIdx.x * 8 + (threadIdx.x >> 5);
    int lane = threadIdx.x & 31;
    const float4* x4 = (const float4*)x;
    const float4* r4 = (const float4*)r;
    float4 xv = x4[(size_t)row * 32 + lane];
    float4 rv = r4[(size_t)row * 32 + lane];
    float4 v = make_float4(xv.x + rv.x, xv.y + rv.y, xv.z + rv.z, xv.w + rv.w);

    float s = v.x + v.y + v.z + v.w;
    float s2 = v.x * v.x + v.y * v.y + v.z * v.z + v.w * v.w;
#pragma unroll
    for (int off = 16; off > 0; off >>= 1) {
        s  += __shfl_xor_sync(0xffffffffu, s, off);
        s2 += __shfl_xor_sync(0xffffffffu, s2, off);
    }
    float mu = s * (1.0f / DD);
    float var = s2 * (1.0f / DD) - mu * mu;
    float inv = rsqrtf(var + LNEPS);

    float4 gw = ((const float4*)g)[lane];
    float4 bw = ((const float4*)b)[lane];
    float4 o;
    o.x = (v.x - mu) * inv * gw.x + bw.x;
    o.y = (v.y - mu) * inv * gw.y + bw.y;
    o.z = (v.z - mu) * inv * gw.z + bw.z;
    o.w = (v.w - mu) * inv * gw.w + bw.w;
    ((float4*)out)[(size_t)row * 32 + lane] = o;
}

__global__ void __launch_bounds__(256) ln_sum4_kernel(
    const float* __restrict__ x, const float* __restrict__ parts,
    const float* __restrict__ fb, const float* __restrict__ g,
    const float* __restrict__ b, float* __restrict__ out)
{
    int row = blockIdx.x * 8 + (threadIdx.x >> 5);
    int lane = threadIdx.x & 31;
    size_t i = (size_t)row * 32 + lane;
    const size_t ps = (size_t)NN * 32;    // float4 stride between partials
    const float4* p4 = (const float4*)parts;
    float4 v = ((const float4*)x)[i];
    float4 fbv = ((const float4*)fb)[lane];
    v.x += fbv.x; v.y += fbv.y; v.z += fbv.z; v.w += fbv.w;
#pragma unroll
    for (int zz = 0; zz < FSPLIT; zz++) {
        float4 p = p4[i + zz * ps];
        v.x += p.x; v.y += p.y; v.z += p.z; v.w += p.w;
    }

    float s = v.x + v.y + v.z + v.w;
    float s2 = v.x * v.x + v.y * v.y + v.z * v.z + v.w * v.w;
#pragma unroll
    for (int off = 16; off > 0; off >>= 1) {
        s  += __shfl_xor_sync(0xffffffffu, s, off);
        s2 += __shfl_xor_sync(0xffffffffu, s2, off);
    }
    float mu = s * (1.0f / DD);
    float var = s2 * (1.0f / DD) - mu * mu;
    float inv = rsqrtf(var + LNEPS);

    float4 gw = ((const float4*)g)[lane];
    float4 bw = ((const float4*)b)[lane];
    float4 o;
    o.x = (v.x - mu) * inv * gw.x + bw.x;
    o.y = (v.y - mu) * inv * gw.y + bw.y;
    o.z = (v.z - mu) * inv * gw.z + bw.z;
    o.w = (v.w - mu) * inv * gw.w + bw.w;
    ((float4*)out)[i] = o;
}

// ---------------- GCN graph preprocessing ---------------------------------
__global__ void zero_cnt_kernel() {
    int i = blockIdx.x * blockDim.x + threadIdx.x;
    if (i < NN) g_cnt[i] = 0;
}
__global__ void count_kernel(const int* __restrict__ dst) {
    int e = blockIdx.x * blockDim.x + threadIdx.x;
    if (e < EE) atomicAdd(&g_cnt[dst[e]], 1);
}
__global__ void dinv_kernel() {
    int i = blockIdx.x * blockDim.x + threadIdx.x;
    if (i < NN) g_dinv[i] = rsqrtf((float)g_cnt[i] + 1.0f);
}
__global__ void scan_kernel() {
    __shared__ int sh[1024];
    int t = threadIdx.x;
    int base = t * 4;
    int c0 = g_cnt[base + 0], c1 = g_cnt[base + 1];
    int c2 = g_cnt[base + 2], c3 = g_cnt[base + 3];
    int local = c0 + c1 + c2 + c3;
    sh[t] = local;
    __syncthreads();
    for (int off = 1; off < 1024; off <<= 1) {
        int v = (t >= off) ? sh[t - off] : 0;
        __syncthreads();
        sh[t] += v;
        __syncthreads();
    }
    int excl = sh[t] - local;
    int p0 = excl, p1 = excl + c0, p2 = p1 + c1, p3 = p2 + c2;
    g_rowptr[base + 0] = p0; g_rowptr[base + 1] = p1;
    g_rowptr[base + 2] = p2; g_rowptr[base + 3] = p3;
    g_fillpos[base + 0] = p0; g_fillpos[base + 1] = p1;
    g_fillpos[base + 2] = p2; g_fillpos[base + 3] = p3;
    if (t == 1023) g_rowptr[NN] = excl + local;
}
__global__ void fill_kernel(const int* __restrict__ src, const int* __restrict__ dst) {
    int e = blockIdx.x * blockDim.x + threadIdx.x;
    if (e < EE) {
        int d = dst[e];
        int pos = atomicAdd(&g_fillpos[d], 1);
        g_col[pos] = src[e];
    }
}

// ---------------- GCN aggregation: gather over CSR -------------------------
template<int F, bool RELU>
__global__ void gather_kernel(const float* __restrict__ hw,
                              const float* __restrict__ bias,
                              float* __restrict__ out)
{
    constexpr int TPR = F / 4;
    constexpr int RPB = 256 / TPR;
    int tid = threadIdx.x;
    int r = blockIdx.x * RPB + tid / TPR;
    int lane = tid % TPR;
    const float4* hw4 = (const float4*)hw;

    float dr = g_dinv[r];
    float4 acc = hw4[(size_t)r * TPR + lane];
    float self = dr * dr;
    acc.x *= self; acc.y *= self; acc.z *= self; acc.w *= self;

    int p1 = g_rowptr[r + 1];
    for (int p = g_rowptr[r]; p < p1; p++) {
        int s = g_col[p];
        float nrm = g_dinv[s] * dr;
        float4 hv = hw4[(size_t)s * TPR + lane];
        acc.x += nrm * hv.x; acc.y += nrm * hv.y;
        acc.z += nrm * hv.z; acc.w += nrm * hv.w;
    }
    if (bias) {
        float4 bb = *(const float4*)&bias[lane * 4];
        acc.x += bb.x; acc.y += bb.y; acc.z += bb.z; acc.w += bb.w;
    }
    if (RELU) {
        acc.x = fmaxf(acc.x, 0.f); acc.y = fmaxf(acc.y, 0.f);
        acc.z = fmaxf(acc.z, 0.f); acc.w = fmaxf(acc.w, 0.f);
    }
    *(float4*)&out[(size_t)r * F + lane * 4] = acc;
}

// ---------------- launch ---------------------------------------------------
extern "C" void kernel_launch(void* const* d_in, const int* in_sizes, int n_in,
                              void* d_out, int out_size)
{
    const float* x          = (const float*)d_in[0];
    const int*   edge_index = (const int*)  d_in[1];
    const float* in_proj_w  = (const float*)d_in[2];
    const float* in_proj_b  = (const float*)d_in[3];
    const float* out_proj_w = (const float*)d_in[4];
    const float* out_proj_b = (const float*)d_in[5];
    const float* ln1_g      = (const float*)d_in[6];
    const float* ln1_b      = (const float*)d_in[7];
    const float* ffn_w1     = (const float*)d_in[8];
    const float* ffn_b1     = (const float*)d_in[9];
    const float* ffn_w2     = (const float*)d_in[10];
    const float* ffn_b2     = (const float*)d_in[11];
    const float* ln2_g      = (const float*)d_in[12];
    const float* ln2_b      = (const float*)d_in[13];
    const float* gcn1_w     = (const float*)d_in[14];
    const float* gcn1_b     = (const float*)d_in[15];
    const float* gcn2_w     = (const float*)d_in[16];
    const float* gcn2_b     = (const float*)d_in[17];
    const float* gcn3_w     = (const float*)d_in[18];
    const float* gcn3_b     = (const float*)d_in[19];
    float* out = (float*)d_out;

    const int* src = edge_index;
    const int* dst = edge_index + EE;

    float *p_qkv, *p_ctx, *p_tmp, *p_y, *p_mid, *p_z, *p_f2, *p_hw, *p_h1, *p_h2;
    cudaGetSymbolAddress((void**)&p_qkv,  g_qkv);
    cudaGetSymbolAddress((void**)&p_ctx,  g_ctx);
    cudaGetSymbolAddress((void**)&p_tmp,  g_tmp);
    cudaGetSymbolAddress((void**)&p_y,    g_y);
    cudaGetSymbolAddress((void**)&p_mid,  g_mid);
    cudaGetSymbolAddress((void**)&p_z,    g_z);
    cudaGetSymbolAddress((void**)&p_f2,   g_f2);
    cudaGetSymbolAddress((void**)&p_hw,   g_hw);
    cudaGetSymbolAddress((void**)&p_h1,   g_h1);
    cudaGetSymbolAddress((void**)&p_h2,   g_h2);

    const int SM_G128 = (2 * 128 * STR + 2 * 64 * STR) * 4;   // 67584
    const int SM_G64  = (2 * 64 * STR + 2 * 64 * STR) * 4;    // 45056
    const int SM_ATTN = (4 * 64 * STR + 64 * 68) * 4;         // 62464

    cudaFuncSetAttribute(gemm_tc<128>, cudaFuncAttributeMaxDynamicSharedMemorySize, SM_G128);
    cudaFuncSetAttribute(gemm_tc<64>,  cudaFuncAttributeMaxDynamicSharedMemorySize, SM_G64);
    cudaFuncSetAttribute(attn_tc,      cudaFuncAttributeMaxDynamicSharedMemorySize, SM_ATTN);

    // ---- transformer encoder layer ----
    gemm_tc<128><<<dim3(6, 32), 256, SM_G128>>>(x, in_proj_w, in_proj_b, p_qkv,
                                                NN, 384, DD, 0, DD);
    attn_tc<<<dim3(NN / 64, HH), 128, SM_ATTN>>>(p_qkv, p_ctx);
    gemm_tc<64><<<dim3(2, 64), 128, SM_G64>>>(p_ctx, out_proj_w, out_proj_b, p_tmp,
                                              NN, DD, DD, 0, DD);
    ln_kernel<<<NN / 8, 256>>>(x, p_tmp, ln1_g, ln1_b, p_y);
    gemm_tc<128><<<dim3(32, 32), 256, SM_G128>>>(p_y, ffn_w1, ffn_b1, p_mid,
                                                 NN, DFF, DD, 1, DD);
    gemm_tc<128><<<dim3(2, 32, FSPLIT), 256, SM_G128>>>(p_mid, ffn_w2, nullptr, p_f2,
                                                        NN, DD, DFF, 0, DFF / FSPLIT);
    ln_sum4_kernel<<<NN / 8, 256>>>(p_y, p_f2, ffn_b2, ln2_g, ln2_b, p_z);

    // ---- graph preprocessing (CSR by dst) ----
    zero_cnt_kernel<<<NN / 256, 256>>>();
    count_kernel<<<EE / 256, 256>>>(dst);
    dinv_kernel<<<NN / 256, 256>>>();
    scan_kernel<<<1, 1024>>>();
    fill_kernel<<<EE / 256, 256>>>(src, dst);

    // ---- GCN layer 1: aggregate z (128-wide) first, then project ----
    gather_kernel<DD, false><<<NN / 8, 256>>>(p_z, nullptr, p_tmp);
    gemm_tc<64><<<dim3(4, 64), 128, SM_G64>>>(p_tmp, gcn1_w, gcn1_b, p_h1,
                                              NN, HID, DD, 1, DD);

    // ---- GCN layer 2: project then aggregate (bias+relu in gather) ----
    gemm_tc<64><<<dim3(4, 64), 128, SM_G64>>>(p_h1, gcn2_w, nullptr, p_hw,
                                              NN, HID, HID, 0, HID);
    gather_kernel<HID, true><<<NN / 4, 256>>>(p_hw, gcn2_b, p_h2);

    // ---- GCN layer 3: project (64-wide) then aggregate ----
    gemm_tc<64><<<dim3(1, 64), 128, SM_G64>>>(p_h2, gcn3_w, nullptr, p_hw,
                                              NN, OUTD, HID, 0, HID);
    gather_kernel<OUTD, false><<<NN / 16, 256>>>(p_hw, gcn3_b, out);
}

// round 6
// speedup vs baseline: 4.0841x; 1.0027x over previous
#include <cuda_runtime.h>
#include <cuda_bf16.h>
#include <math_constants.h>

// ---------------- problem constants ----------------
#define NN   4096
#define DD   128
#define HH   4
#define DHH  32
#define DFF  2048
#define HID  256
#define OUTD 64
#define EE   131072
#define LNEPS 1e-5f
#define FSPLIT 4
#define ZSPLIT 2
#define KT_PER ((NN / 64) / ZSPLIT)   // 32 key tiles per split

typedef unsigned u32;

// ---------------- helpers ----------------
__device__ __forceinline__ unsigned smem_u32(const void* p) {
    unsigned a;
    asm("{ .reg .u64 t; cvta.to.shared.u64 t, %1; cvt.u32.u64 %0, t; }"
        : "=r"(a) : "l"(p));
    return a;
}
__device__ __forceinline__ void cp16(u32 saddr, const void* gptr) {
    asm volatile("cp.async.ca.shared.global [%0], [%1], 16;"
                 :: "r"(saddr), "l"(gptr) : "memory");
}
__device__ __forceinline__ void cpcommit() {
    asm volatile("cp.async.commit_group;" ::: "memory");
}
__device__ __forceinline__ void cpwait0() {
    asm volatile("cp.async.wait_group 0;" ::: "memory");
}
__device__ __forceinline__ void cpwait1() {
    asm volatile("cp.async.wait_group 1;" ::: "memory");
}
// round-to-nearest tf32 conversion (keeps error unbiased)
__device__ __forceinline__ u32 f2tf(float x) {
    u32 u; asm("cvt.rna.tf32.f32 %0, %1;" : "=r"(u) : "f"(x));
    return u;
}
__device__ __forceinline__ void mma_tf32(float& d0, float& d1, float& d2, float& d3,
                                         u32 a0, u32 a1, u32 a2, u32 a3,
                                         u32 b0, u32 b1) {
    asm volatile(
        "mma.sync.aligned.m16n8k8.row.col.f32.tf32.tf32.f32 "
        "{%0,%1,%2,%3}, {%4,%5,%6,%7}, {%8,%9}, {%0,%1,%2,%3};\n"
        : "+f"(d0), "+f"(d1), "+f"(d2), "+f"(d3)
        : "r"(a0), "r"(a1), "r"(a2), "r"(a3), "r"(b0), "r"(b1));
}

// ---------------- scratch ----------------
__device__ float g_qkv[NN * 384];
__device__ float g_ctx[NN * DD];
__device__ float g_tmp[NN * DD];     // attn_out; later reused as GCN agg buffer
__device__ float g_y[NN * DD];
__device__ float g_mid[NN * DFF];
__device__ float g_z[NN * DD];
__device__ float g_f2[FSPLIT * NN * DD];
__device__ float g_hw[NN * HID];
__device__ float g_h1[NN * HID];
__device__ float g_h2[NN * HID];
__device__ float g_pm[ZSPLIT * HH * NN];
__device__ float g_pl[ZSPLIT * HH * NN];
__device__ float g_pacc[ZSPLIT * HH * NN * 32];
__device__ float g_dinv[NN];
__device__ int   g_cnt[NN];
__device__ int   g_rowptr[NN + 1];
__device__ int   g_fillpos[NN];
__device__ int   g_col[EE];

// ======================================================================
// tf32 tensor-core GEMM with cp.async double buffering.
// C = A[M,K]*B[Nc,K]^T (+bias)(+relu). Block tile BM x 64, BK=32.
// BM=128: 256 thr (8 warps 4x2). BM=64: 128 thr (4 warps 2x2).
// Fragments RN-converted to tf32 at register load.
// Optional K-split via blockIdx.z (kslice); slice z writes C + z*M*Nc.
// ======================================================================
#define STR 44   // smem row stride in floats (16B-aligned, conflict-free frags)

template<int BM>
__global__ void __launch_bounds__(BM * 2) gemm_tc(
    const float* __restrict__ A, const float* __restrict__ B,
    const float* __restrict__ bias, float* __restrict__ C,
    int M, int Nc, int K, int relu, int kslice)
{
    extern __shared__ float smem[];
    float* As = smem;                  // [2][BM][STR]
    float* Bs = smem + 2 * BM * STR;   // [2][64][STR]
    const int THREADS = BM * 2;

    const int tid = threadIdx.x;
    const int wid = tid >> 5, lane = tid & 31;
    const int g = lane >> 2, t = lane & 3;
    const int warp_m = wid >> 1, warp_n = wid & 1;
    const int row0 = blockIdx.y * BM, col0 = blockIdx.x * 64;
    const int kbeg = blockIdx.z * kslice;
    const int niter = kslice / 32;
    C += (size_t)blockIdx.z * M * Nc;

    const u32 sAa = smem_u32(As), sBa = smem_u32(Bs);

    float acc[2][4][4];
#pragma unroll
    for (int mt = 0; mt < 2; mt++)
#pragma unroll
        for (int nt = 0; nt < 4; nt++)
#pragma unroll
            for (int j = 0; j < 4; j++) acc[mt][nt][j] = 0.0f;

    auto issue = [&](int it, int buf) {
        const float* abase = A + (size_t)row0 * K + kbeg + it * 32;
        u32 ad = sAa + buf * BM * STR * 4;
#pragma unroll
        for (int i = 0; i < 4; i++) {
            int c = tid + i * THREADS;          // BM*8 chunks
            int rr = c >> 3, kc = (c & 7) * 4;
            cp16(ad + (rr * STR + kc) * 4, abase + (size_t)rr * K + kc);
        }
        const float* bbase = B + (size_t)col0 * K + kbeg + it * 32;
        u32 bd = sBa + buf * 64 * STR * 4;
#pragma unroll
        for (int i = 0; i < 512 / (BM * 2); i++) {
            int c = tid + i * THREADS;          // 512 chunks
            int rr = c >> 3, kc = (c & 7) * 4;
            cp16(bd + (rr * STR + kc) * 4, bbase + (size_t)rr * K + kc);
        }
        cpcommit();
    };

    issue(0, 0);
    for (int it = 0; it < niter; it++) {
        if (it + 1 < niter) issue(it + 1, (it + 1) & 1);
        if (it + 1 < niter) cpwait1(); else cpwait0();
        __syncthreads();

        const float* Ab = As + (it & 1) * BM * STR;
        const float* Bb = Bs + (it & 1) * 64 * STR;
#pragma unroll
        for (int ks = 0; ks < 4; ks++) {
            u32 af[2][4];
#pragma unroll
            for (int mt = 0; mt < 2; mt++) {
                int rb = warp_m * 32 + mt * 16;
                af[mt][0] = f2tf(Ab[(rb + g) * STR + ks * 8 + t]);
                af[mt][1] = f2tf(Ab[(rb + g + 8) * STR + ks * 8 + t]);
                af[mt][2] = f2tf(Ab[(rb + g) * STR + ks * 8 + t + 4]);
                af[mt][3] = f2tf(Ab[(rb + g + 8) * STR + ks * 8 + t + 4]);
            }
#pragma unroll
            for (int nt = 0; nt < 4; nt++) {
                int nb = warp_n * 32 + nt * 8;
                u32 b0 = f2tf(Bb[(nb + g) * STR + ks * 8 + t]);
                u32 b1 = f2tf(Bb[(nb + g) * STR + ks * 8 + t + 4]);
#pragma unroll
                for (int mt = 0; mt < 2; mt++)
                    mma_tf32(acc[mt][nt][0], acc[mt][nt][1], acc[mt][nt][2], acc[mt][nt][3],
                             af[mt][0], af[mt][1], af[mt][2], af[mt][3], b0, b1);
            }
        }
        __syncthreads();
    }

#pragma unroll
    for (int mt = 0; mt < 2; mt++) {
        int r0 = row0 + warp_m * 32 + mt * 16 + g;
#pragma unroll
        for (int nt = 0; nt < 4; nt++) {
            int c0i = col0 + warp_n * 32 + nt * 8 + 2 * t;
            float b0 = 0.f, b1 = 0.f;
            if (bias) { b0 = bias[c0i]; b1 = bias[c0i + 1]; }
            float v0 = acc[mt][nt][0] + b0, v1 = acc[mt][nt][1] + b1;
            float v2 = acc[mt][nt][2] + b0, v3 = acc[mt][nt][3] + b1;
            if (relu) {
                v0 = fmaxf(v0, 0.f); v1 = fmaxf(v1, 0.f);
                v2 = fmaxf(v2, 0.f); v3 = fmaxf(v3, 0.f);
            }
            *(float2*)&C[(size_t)r0 * Nc + c0i] = make_float2(v0, v1);
            *(float2*)&C[(size_t)(r0 + 8) * Nc + c0i] = make_float2(v2, v3);
        }
    }
}

// ======================================================================
// Flash attention, tf32 mma, cp.async double-buffered K/V, K-split x2.
// Block = 64 queries x 1 head x half the keys; 128 threads (4 warps).
// Writes unnormalized partial O + (m, l) per row; combine kernel merges.
// ======================================================================
#define PSTR 36   // sP row stride (36 mod 32 == 4 -> conflict-free frag reads)

__global__ void __launch_bounds__(128) attn_tc(const float* __restrict__ qkv,
                                               float* __restrict__ pm,
                                               float* __restrict__ pl,
                                               float* __restrict__ pacc)
{
    extern __shared__ float smem[];
    float* sK = smem;                   // [2][64][STR]
    float* sV = smem + 2 * 64 * STR;    // [2][64][STR]
    float* sQ = smem + 4 * 64 * STR;    // [64][STR], reused as sP [64][PSTR]
    u32*   sP = (u32*)sQ;

    const int h = blockIdx.y, z = blockIdx.z;
    const int q0 = blockIdx.x * 64;
    const int tid = threadIdx.x;
    const int wid = tid >> 5, lane = tid & 31;
    const int g = lane >> 2, t = lane & 3;
    const int rb = wid * 16;
    const float SCALE = 0.17677669529663687f;   // 1/sqrt(32)

    const int qoff = h * 32;
    const int koff = DD + h * 32;
    const int voff = 2 * DD + h * 32;
    const int kt_beg = z * KT_PER, kt_end = kt_beg + KT_PER;

    const u32 sKa = smem_u32(sK), sVa = smem_u32(sV), sQa = smem_u32(sQ);

    // stage Q (group 0)
#pragma unroll
    for (int i = 0; i < 4; i++) {
        int c = tid + i * 128;
        int rr = c >> 3, kc = (c & 7) * 4;
        cp16(sQa + (rr * STR + kc) * 4, &qkv[(size_t)(q0 + rr) * 384 + qoff + kc]);
    }
    cpcommit();

    auto issueKV = [&](int kt, int buf) {
#pragma unroll
        for (int i = 0; i < 4; i++) {
            int c = tid + i * 128;
            int rr = c >> 3, kc = (c & 7) * 4;
            const float* base = &qkv[(size_t)(kt * 64 + rr) * 384];
            cp16(sKa + (buf * 64 * STR + rr * STR + kc) * 4, base + koff + kc);
            cp16(sVa + (buf * 64 * STR + rr * STR + kc) * 4, base + voff + kc);
        }
        cpcommit();
    };

    issueKV(kt_beg, 0);
    cpwait1();              // Q group done (KV0 may be in flight)
    __syncthreads();

    // Q fragments, pre-scaled by 1/sqrt(dh), RN tf32
    u32 qf[4][4];
#pragma unroll
    for (int ks = 0; ks < 4; ks++) {
        qf[ks][0] = f2tf(sQ[(rb + g) * STR + ks * 8 + t] * SCALE);
        qf[ks][1] = f2tf(sQ[(rb + g + 8) * STR + ks * 8 + t] * SCALE);
        qf[ks][2] = f2tf(sQ[(rb + g) * STR + ks * 8 + t + 4] * SCALE);
        qf[ks][3] = f2tf(sQ[(rb + g + 8) * STR + ks * 8 + t + 4] * SCALE);
    }

    float O[4][4];
#pragma unroll
    for (int nt = 0; nt < 4; nt++)
#pragma unroll
        for (int j = 0; j < 4; j++) O[nt][j] = 0.0f;
    float m_g = -CUDART_INF_F, m_g8 = -CUDART_INF_F;
    float lg = 0.0f, lg8 = 0.0f;

    for (int kt = kt_beg; kt < kt_end; kt++) {
        if (kt + 1 < kt_end) issueKV(kt + 1, (kt + 1) & 1);
        if (kt + 1 < kt_end) cpwait1(); else cpwait0();
        __syncthreads();

        const float* K_ = sK + (kt & 1) * 64 * STR;
        const float* V_ = sV + (kt & 1) * 64 * STR;

        // S = Q K^T (16 x 64 per warp)
        float sc[8][4];
#pragma unroll
        for (int nt = 0; nt < 8; nt++)
#pragma unroll
            for (int j = 0; j < 4; j++) sc[nt][j] = 0.0f;
#pragma unroll
        for (int ks = 0; ks < 4; ks++) {
#pragma unroll
            for (int nt = 0; nt < 8; nt++) {
                u32 b0 = f2tf(K_[(nt * 8 + g) * STR + ks * 8 + t]);
                u32 b1 = f2tf(K_[(nt * 8 + g) * STR + ks * 8 + t + 4]);
                mma_tf32(sc[nt][0], sc[nt][1], sc[nt][2], sc[nt][3],
                         qf[ks][0], qf[ks][1], qf[ks][2], qf[ks][3], b0, b1);
            }
        }

        // row maxima (rows g and g+8)
        float rg = -CUDART_INF_F, rg8 = -CUDART_INF_F;
#pragma unroll
        for (int nt = 0; nt < 8; nt++) {
            rg  = fmaxf(rg,  fmaxf(sc[nt][0], sc[nt][1]));
            rg8 = fmaxf(rg8, fmaxf(sc[nt][2], sc[nt][3]));
        }
        rg  = fmaxf(rg,  __shfl_xor_sync(0xffffffffu, rg, 1));
        rg  = fmaxf(rg,  __shfl_xor_sync(0xffffffffu, rg, 2));
        rg8 = fmaxf(rg8, __shfl_xor_sync(0xffffffffu, rg8, 1));
        rg8 = fmaxf(rg8, __shfl_xor_sync(0xffffffffu, rg8, 2));

        float mng = fmaxf(m_g, rg),   fg  = __expf(m_g - mng);
        float mng8 = fmaxf(m_g8, rg8), fg8 = __expf(m_g8 - mng8);
        m_g = mng; m_g8 = mng8;
        lg *= fg; lg8 *= fg8;
#pragma unroll
        for (int nt = 0; nt < 4; nt++) {
            O[nt][0] *= fg;  O[nt][1] *= fg;
            O[nt][2] *= fg8; O[nt][3] *= fg8;
        }

        // P = exp(S - m) -> sP (tf32 RN)
#pragma unroll
        for (int nt = 0; nt < 8; nt++) {
            float p0 = __expf(sc[nt][0] - m_g);
            float p1 = __expf(sc[nt][1] - m_g);
            float p2 = __expf(sc[nt][2] - m_g8);
            float p3 = __expf(sc[nt][3] - m_g8);
            lg += p0 + p1; lg8 += p2 + p3;
            int cc = nt * 8 + 2 * t;
            sP[(rb + g) * PSTR + cc] = f2tf(p0);     sP[(rb + g) * PSTR + cc + 1] = f2tf(p1);
            sP[(rb + g + 8) * PSTR + cc] = f2tf(p2); sP[(rb + g + 8) * PSTR + cc + 1] = f2tf(p3);
        }
        __syncwarp();

        // O += P V
#pragma unroll
        for (int ks = 0; ks < 8; ks++) {
            u32 a0 = sP[(rb + g) * PSTR + ks * 8 + t];
            u32 a1 = sP[(rb + g + 8) * PSTR + ks * 8 + t];
            u32 a2 = sP[(rb + g) * PSTR + ks * 8 + t + 4];
            u32 a3 = sP[(rb + g + 8) * PSTR + ks * 8 + t + 4];
#pragma unroll
            for (int nt = 0; nt < 4; nt++) {
                u32 b0 = f2tf(V_[(ks * 8 + t) * STR + nt * 8 + g]);
                u32 b1 = f2tf(V_[(ks * 8 + t + 4) * STR + nt * 8 + g]);
                mma_tf32(O[nt][0], O[nt][1], O[nt][2], O[nt][3],
                         a0, a1, a2, a3, b0, b1);
            }
        }
        __syncthreads();
    }

    // quad-reduce l; write unnormalized partials
    lg  += __shfl_xor_sync(0xffffffffu, lg, 1);
    lg  += __shfl_xor_sync(0xffffffffu, lg, 2);
    lg8 += __shfl_xor_sync(0xffffffffu, lg8, 1);
    lg8 += __shfl_xor_sync(0xffffffffu, lg8, 2);

    const int prow = (z * HH + h) * NN + q0 + rb + g;   // row index in partials
    if (t == 0) {
        pm[prow] = m_g;      pm[prow + 8] = m_g8;
        pl[prow] = lg;       pl[prow + 8] = lg8;
    }
    float* op0 = pacc + (size_t)prow * 32;
    float* op8 = pacc + (size_t)(prow + 8) * 32;
#pragma unroll
    for (int nt = 0; nt < 4; nt++) {
        int cc = nt * 8 + 2 * t;
        *(float2*)&op0[cc] = make_float2(O[nt][0], O[nt][1]);
        *(float2*)&op8[cc] = make_float2(O[nt][2], O[nt][3]);
    }
}

// merge ZSPLIT=2 partials -> ctx (exact flash-attention merge)
__global__ void __launch_bounds__(256) attn_combine(const float* __restrict__ pm,
                                                    const float* __restrict__ pl,
                                                    const float* __restrict__ pacc,
                                                    float* __restrict__ ctx)
{
    int row = blockIdx.x * 8 + (threadIdx.x >> 5);   // 0 .. HH*NN-1
    int lane = threadIdx.x & 31;
    int h = row >> 12, n = row & (NN - 1);
    const int OFF = HH * NN;
    float m0 = pm[row], m1 = pm[OFF + row];
    float mm = fmaxf(m0, m1);
    float w0 = __expf(m0 - mm), w1 = __expf(m1 - mm);
    float l = pl[row] * w0 + pl[OFF + row] * w1;
    float o = pacc[(size_t)row * 32 + lane] * w0
            + pacc[(size_t)(OFF + row) * 32 + lane] * w1;
    ctx[(size_t)n * DD + h * 32 + lane] = o / l;
}

// ---------------- residual + LayerNorm: 2 rows per warp --------------------
// Also zeroes g_cnt (first 16 blocks) so the count kernel can follow.
__global__ void __launch_bounds__(256) ln_kernel(
    const float* __restrict__ x, const float* __restrict__ r,
    const float* __restrict__ g, const float* __restrict__ b,
    float* __restrict__ out)
{
    int w = blockIdx.x * 8 + (threadIdx.x >> 5);    // 0 .. NN/2-1
    int lane = threadIdx.x & 31;
    size_t iA = (size_t)(2 * w) * 32 + lane, iB = iA + 32;
    const float4* x4 = (const float4*)x;
    const float4* r4 = (const float4*)r;
    float4 xa = x4[iA], ra = r4[iA];
    float4 xb = x4[iB], rb_ = r4[iB];
    float4 va = make_float4(xa.x + ra.x, xa.y + ra.y, xa.z + ra.z, xa.w + ra.w);
    float4 vb = make_float4(xb.x + rb_.x, xb.y + rb_.y, xb.z + rb_.z, xb.w + rb_.w);

    float sA = va.x + va.y + va.z + va.w;
    float qA = va.x * va.x + va.y * va.y + va.z * va.z + va.w * va.w;
    float sB = vb.x + vb.y + vb.z + vb.w;
    float qB = vb.x * vb.x + vb.y * vb.y + vb.z * vb.z + vb.w * vb.w;
#pragma unroll
    for (int off = 16; off > 0; off >>= 1) {
        sA += __shfl_xor_sync(0xffffffffu, sA, off);
        qA += __shfl_xor_sync(0xffffffffu, qA, off);
        sB += __shfl_xor_sync(0xffffffffu, sB, off);
        qB += __shfl_xor_sync(0xffffffffu, qB, off);
    }
    float muA = sA * (1.0f / DD), muB = sB * (1.0f / DD);
    float invA = rsqrtf(qA * (1.0f / DD) - muA * muA + LNEPS);
    float invB = rsqrtf(qB * (1.0f / DD) - muB * muB + LNEPS);

    float4 gw = ((const float4*)g)[lane];
    float4 bw = ((const float4*)b)[lane];
    float4 oA, oB;
    oA.x = (va.x - muA) * invA * gw.x + bw.x;
    oA.y = (va.y - muA) * invA * gw.y + bw.y;
    oA.z = (va.z - muA) * invA * gw.z + bw.z;
    oA.w = (va.w - muA) * invA * gw.w + bw.w;
    oB.x = (vb.x - muB) * invB * gw.x + bw.x;
    oB.y = (vb.y - muB) * invB * gw.y + bw.y;
    oB.z = (vb.z - muB) * invB * gw.z + bw.z;
    oB.w = (vb.w - muB) * invB * gw.w + bw.w;
    ((float4*)out)[iA] = oA;
    ((float4*)out)[iB] = oB;

    if (blockIdx.x < 16) g_cnt[blockIdx.x * 256 + threadIdx.x] = 0;
}

__global__ void __launch_bounds__(256) ln_sum4_kernel(
    const float* __restrict__ x, const float* __restrict__ parts,
    const float* __restrict__ fb, const float* __restrict__ g,
    const float* __restrict__ b, float* __restrict__ out)
{
    int row = blockIdx.x * 8 + (threadIdx.x >> 5);
    int lane = threadIdx.x & 31;
    size_t i = (size_t)row * 32 + lane;
    const size_t ps = (size_t)NN * 32;    // float4 stride between partials
    const float4* p4 = (const float4*)parts;
    float4 v = ((const float4*)x)[i];
    float4 fbv = ((const float4*)fb)[lane];
    v.x += fbv.x; v.y += fbv.y; v.z += fbv.z; v.w += fbv.w;
#pragma unroll
    for (int zz = 0; zz < FSPLIT; zz++) {
        float4 p = p4[i + zz * ps];
        v.x += p.x; v.y += p.y; v.z += p.z; v.w += p.w;
    }

    float s = v.x + v.y + v.z + v.w;
    float s2 = v.x * v.x + v.y * v.y + v.z * v.z + v.w * v.w;
#pragma unroll
    for (int off = 16; off > 0; off >>= 1) {
        s  += __shfl_xor_sync(0xffffffffu, s, off);
        s2 += __shfl_xor_sync(0xffffffffu, s2, off);
    }
    float mu = s * (1.0f / DD);
    float var = s2 * (1.0f / DD) - mu * mu;
    float inv = rsqrtf(var + LNEPS);

    float4 gw = ((const float4*)g)[lane];
    float4 bw = ((const float4*)b)[lane];
    float4 o;
    o.x = (v.x - mu) * inv * gw.x + bw.x;
    o.y = (v.y - mu) * inv * gw.y + bw.y;
    o.z = (v.z - mu) * inv * gw.z + bw.z;
    o.w = (v.w - mu) * inv * gw.w + bw.w;
    ((float4*)out)[i] = o;
}

// ---------------- GCN graph preprocessing ---------------------------------
__global__ void count_kernel(const int* __restrict__ dst) {
    int e = blockIdx.x * blockDim.x + threadIdx.x;
    if (e < EE) atomicAdd(&g_cnt[dst[e]], 1);
}
// single-block scan over 4096 counts -> rowptr / fillpos; also dinv
__global__ void scan_kernel() {
    __shared__ int sh[1024];
    int t = threadIdx.x;
    int base = t * 4;
    int c0 = g_cnt[base + 0], c1 = g_cnt[base + 1];
    int c2 = g_cnt[base + 2], c3 = g_cnt[base + 3];
    g_dinv[base + 0] = rsqrtf((float)c0 + 1.0f);
    g_dinv[base + 1] = rsqrtf((float)c1 + 1.0f);
    g_dinv[base + 2] = rsqrtf((float)c2 + 1.0f);
    g_dinv[base + 3] = rsqrtf((float)c3 + 1.0f);
    int local = c0 + c1 + c2 + c3;
    sh[t] = local;
    __syncthreads();
    for (int off = 1; off < 1024; off <<= 1) {
        int v = (t >= off) ? sh[t - off] : 0;
        __syncthreads();
        sh[t] += v;
        __syncthreads();
    }
    int excl = sh[t] - local;
    int p0 = excl, p1 = excl + c0, p2 = p1 + c1, p3 = p2 + c2;
    g_rowptr[base + 0] = p0; g_rowptr[base + 1] = p1;
    g_rowptr[base + 2] = p2; g_rowptr[base + 3] = p3;
    g_fillpos[base + 0] = p0; g_fillpos[base + 1] = p1;
    g_fillpos[base + 2] = p2; g_fillpos[base + 3] = p3;
    if (t == 1023) g_rowptr[NN] = excl + local;
}
__global__ void fill_kernel(const int* __restrict__ src, const int* __restrict__ dst) {
    int e = blockIdx.x * blockDim.x + threadIdx.x;
    if (e < EE) {
        int d = dst[e];
        int pos = atomicAdd(&g_fillpos[d], 1);
        g_col[pos] = src[e];
    }
}

// ---------------- GCN aggregation: gather over CSR, 1-deep prefetch --------
template<int F, bool RELU>
__global__ void gather_kernel(const float* __restrict__ hw,
                              const float* __restrict__ bias,
                              float* __restrict__ out)
{
    constexpr int TPR = F / 4;
    constexpr int RPB = 256 / TPR;
    int tid = threadIdx.x;
    int r = blockIdx.x * RPB + tid / TPR;
    int lane = tid % TPR;
    const float4* hw4 = (const float4*)hw;

    float dr = g_dinv[r];
    float4 acc = hw4[(size_t)r * TPR + lane];
    float selfw = dr * dr;
    acc.x *= selfw; acc.y *= selfw; acc.z *= selfw; acc.w *= selfw;

    int p0 = g_rowptr[r], p1 = g_rowptr[r + 1];
    if (p0 < p1) {
        int s = g_col[p0];
        float4 hv = hw4[(size_t)s * TPR + lane];
        float ds = g_dinv[s];
        for (int p = p0 + 1; p < p1; p++) {
            int s2 = g_col[p];
            float4 hv2 = hw4[(size_t)s2 * TPR + lane];
            float ds2 = g_dinv[s2];
            float nrm = ds * dr;
            acc.x += nrm * hv.x; acc.y += nrm * hv.y;
            acc.z += nrm * hv.z; acc.w += nrm * hv.w;
            hv = hv2; ds = ds2;
        }
        float nrm = ds * dr;
        acc.x += nrm * hv.x; acc.y += nrm * hv.y;
        acc.z += nrm * hv.z; acc.w += nrm * hv.w;
    }
    if (bias) {
        float4 bb = *(const float4*)&bias[lane * 4];
        acc.x += bb.x; acc.y += bb.y; acc.z += bb.z; acc.w += bb.w;
    }
    if (RELU) {
        acc.x = fmaxf(acc.x, 0.f); acc.y = fmaxf(acc.y, 0.f);
        acc.z = fmaxf(acc.z, 0.f); acc.w = fmaxf(acc.w, 0.f);
    }
    *(float4*)&out[(size_t)r * F + lane * 4] = acc;
}

// ---------------- launch ---------------------------------------------------
extern "C" void kernel_launch(void* const* d_in, const int* in_sizes, int n_in,
                              void* d_out, int out_size)
{
    const float* x          = (const float*)d_in[0];
    const int*   edge_index = (const int*)  d_in[1];
    const float* in_proj_w  = (const float*)d_in[2];
    const float* in_proj_b  = (const float*)d_in[3];
    const float* out_proj_w = (const float*)d_in[4];
    const float* out_proj_b = (const float*)d_in[5];
    const float* ln1_g      = (const float*)d_in[6];
    const float* ln1_b      = (const float*)d_in[7];
    const float* ffn_w1     = (const float*)d_in[8];
    const float* ffn_b1     = (const float*)d_in[9];
    const float* ffn_w2     = (const float*)d_in[10];
    const float* ffn_b2     = (const float*)d_in[11];
    const float* ln2_g      = (const float*)d_in[12];
    const float* ln2_b      = (const float*)d_in[13];
    const float* gcn1_w     = (const float*)d_in[14];
    const float* gcn1_b     = (const float*)d_in[15];
    const float* gcn2_w     = (const float*)d_in[16];
    const float* gcn2_b     = (const float*)d_in[17];
    const float* gcn3_w     = (const float*)d_in[18];
    const float* gcn3_b     = (const float*)d_in[19];
    float* out = (float*)d_out;

    const int* src = edge_index;
    const int* dst = edge_index + EE;

    float *p_qkv, *p_ctx, *p_tmp, *p_y, *p_mid, *p_z, *p_f2, *p_hw, *p_h1, *p_h2;
    float *p_pm, *p_pl, *p_pacc;
    cudaGetSymbolAddress((void**)&p_qkv,  g_qkv);
    cudaGetSymbolAddress((void**)&p_ctx,  g_ctx);
    cudaGetSymbolAddress((void**)&p_tmp,  g_tmp);
    cudaGetSymbolAddress((void**)&p_y,    g_y);
    cudaGetSymbolAddress((void**)&p_mid,  g_mid);
    cudaGetSymbolAddress((void**)&p_z,    g_z);
    cudaGetSymbolAddress((void**)&p_f2,   g_f2);
    cudaGetSymbolAddress((void**)&p_hw,   g_hw);
    cudaGetSymbolAddress((void**)&p_h1,   g_h1);
    cudaGetSymbolAddress((void**)&p_h2,   g_h2);
    cudaGetSymbolAddress((void**)&p_pm,   g_pm);
    cudaGetSymbolAddress((void**)&p_pl,   g_pl);
    cudaGetSymbolAddress((void**)&p_pacc, g_pacc);

    const int SM_G128 = (2 * 128 * STR + 2 * 64 * STR) * 4;   // 67584
    const int SM_G64  = (2 * 64 * STR + 2 * 64 * STR) * 4;    // 45056
    const int SM_ATTN = (5 * 64 * STR) * 4;                   // 56320 -> 4 blocks/SM

    cudaFuncSetAttribute(gemm_tc<128>, cudaFuncAttributeMaxDynamicSharedMemorySize, SM_G128);
    cudaFuncSetAttribute(gemm_tc<64>,  cudaFuncAttributeMaxDynamicSharedMemorySize, SM_G64);
    cudaFuncSetAttribute(attn_tc,      cudaFuncAttributeMaxDynamicSharedMemorySize, SM_ATTN);

    // ---- transformer encoder layer ----
    gemm_tc<128><<<dim3(6, 32), 256, SM_G128>>>(x, in_proj_w, in_proj_b, p_qkv,
                                                NN, 384, DD, 0, DD);
    attn_tc<<<dim3(NN / 64, HH, ZSPLIT), 128, SM_ATTN>>>(p_qkv, p_pm, p_pl, p_pacc);
    attn_combine<<<HH * NN / 8, 256>>>(p_pm, p_pl, p_pacc, p_ctx);
    gemm_tc<64><<<dim3(2, 64), 128, SM_G64>>>(p_ctx, out_proj_w, out_proj_b, p_tmp,
                                              NN, DD, DD, 0, DD);
    ln_kernel<<<NN / 16, 256>>>(x, p_tmp, ln1_g, ln1_b, p_y);   // also zeroes g_cnt
    gemm_tc<128><<<dim3(32, 32), 256, SM_G128>>>(p_y, ffn_w1, ffn_b1, p_mid,
                                                 NN, DFF, DD, 1, DD);
    gemm_tc<128><<<dim3(2, 32, FSPLIT), 256, SM_G128>>>(p_mid, ffn_w2, nullptr, p_f2,
                                                        NN, DD, DFF, 0, DFF / FSPLIT);
    ln_sum4_kernel<<<NN / 8, 256>>>(p_y, p_f2, ffn_b2, ln2_g, ln2_b, p_z);

    // ---- graph preprocessing (CSR by dst; g_cnt zeroed by ln_kernel) ----
    count_kernel<<<EE / 256, 256>>>(dst);
    scan_kernel<<<1, 1024>>>();          // rowptr + fillpos + dinv
    fill_kernel<<<EE / 256, 256>>>(src, dst);

    // ---- GCN layer 1: aggregate z (128-wide) first, then project ----
    gather_kernel<DD, false><<<NN / 8, 256>>>(p_z, nullptr, p_tmp);
    gemm_tc<64><<<dim3(4, 64), 128, SM_G64>>>(p_tmp, gcn1_w, gcn1_b, p_h1,
                                              NN, HID, DD, 1, DD);

    // ---- GCN layer 2: project then aggregate (bias+relu in gather) ----
    gemm_tc<64><<<dim3(4, 64), 128, SM_G64>>>(p_h1, gcn2_w, nullptr, p_hw,
                                              NN, HID, HID, 0, HID);
    gather_kernel<HID, true><<<NN / 4, 256>>>(p_hw, gcn2_b, p_h2);

    // ---- GCN layer 3: project (64-wide) then aggregate ----
    gemm_tc<64><<<dim3(1, 64), 128, SM_G64>>>(p_h2, gcn3_w, nullptr, p_hw,
                                              NN, OUTD, HID, 0, HID);
    gather_kernel<OUTD, false><<<NN / 16, 256>>>(p_hw, gcn3_b, out);
}

// round 7
// speedup vs baseline: 4.1571x; 1.0179x over previous
#include <cuda_runtime.h>
#include <cuda_bf16.h>
#include <math_constants.h>

// ---------------- problem constants ----------------
#define NN   4096
#define DD   128
#define HH   4
#define DHH  32
#define DFF  2048
#define HID  256
#define OUTD 64
#define EE   131072
#define LNEPS 1e-5f
#define FSPLIT 4
#define ZSPLIT 2
#define QB   128                      // queries per attention block
#define KT_PER ((NN / 64) / ZSPLIT)   // 32 key tiles per split

typedef unsigned u32;

// ---------------- helpers ----------------
__device__ __forceinline__ unsigned smem_u32(const void* p) {
    unsigned a;
    asm("{ .reg .u64 t; cvta.to.shared.u64 t, %1; cvt.u32.u64 %0, t; }"
        : "=r"(a) : "l"(p));
    return a;
}
__device__ __forceinline__ void cp16(u32 saddr, const void* gptr) {
    asm volatile("cp.async.ca.shared.global [%0], [%1], 16;"
                 :: "r"(saddr), "l"(gptr) : "memory");
}
__device__ __forceinline__ void cpcommit() {
    asm volatile("cp.async.commit_group;" ::: "memory");
}
__device__ __forceinline__ void cpwait0() {
    asm volatile("cp.async.wait_group 0;" ::: "memory");
}
__device__ __forceinline__ void cpwait1() {
    asm volatile("cp.async.wait_group 1;" ::: "memory");
}
// round-to-nearest tf32 conversion (keeps error unbiased)
__device__ __forceinline__ u32 f2tf(float x) {
    u32 u; asm("cvt.rna.tf32.f32 %0, %1;" : "=r"(u) : "f"(x));
    return u;
}
__device__ __forceinline__ void mma_tf32(float& d0, float& d1, float& d2, float& d3,
                                         u32 a0, u32 a1, u32 a2, u32 a3,
                                         u32 b0, u32 b1) {
    asm volatile(
        "mma.sync.aligned.m16n8k8.row.col.f32.tf32.tf32.f32 "
        "{%0,%1,%2,%3}, {%4,%5,%6,%7}, {%8,%9}, {%0,%1,%2,%3};\n"
        : "+f"(d0), "+f"(d1), "+f"(d2), "+f"(d3)
        : "r"(a0), "r"(a1), "r"(a2), "r"(a3), "r"(b0), "r"(b1));
}

// ---------------- scratch ----------------
__device__ float g_qkv[NN * 384];
__device__ float g_ctx[NN * DD];
__device__ float g_tmp[NN * DD];     // attn_out; later reused as GCN agg buffer
__device__ float g_y[NN * DD];
__device__ float g_mid[NN * DFF];
__device__ float g_z[NN * DD];
__device__ float g_f2[FSPLIT * NN * DD];
__device__ float g_hw[NN * HID];
__device__ float g_h1[NN * HID];
__device__ float g_h2[NN * HID];
__device__ float g_pm[ZSPLIT * HH * NN];
__device__ float g_pl[ZSPLIT * HH * NN];
__device__ float g_pacc[ZSPLIT * HH * NN * 32];
__device__ float g_dinv[NN];
__device__ int   g_cnt[NN];
__device__ int   g_rowptr[NN + 1];
__device__ int   g_fillpos[NN];
__device__ int   g_col[EE];

// ======================================================================
// tf32 tensor-core GEMM with cp.async double buffering.
// C = A[M,K]*B[Nc,K]^T (+bias)(+relu). Block tile BM x 64, BK=32.
// mode=1 (qkv): output pre-rounded to tf32; first DD columns (q) also
// pre-scaled by 1/sqrt(dh). Lets attention skip all cvt instructions.
// ======================================================================
#define STR 44   // smem row stride in floats (16B-aligned, conflict-free frags)
#define ATT_SCALE 0.17677669529663687f

template<int BM>
__global__ void __launch_bounds__(BM * 2) gemm_tc(
    const float* __restrict__ A, const float* __restrict__ B,
    const float* __restrict__ bias, float* __restrict__ C,
    int M, int Nc, int K, int relu, int kslice, int mode)
{
    extern __shared__ float smem[];
    float* As = smem;                  // [2][BM][STR]
    float* Bs = smem + 2 * BM * STR;   // [2][64][STR]
    const int THREADS = BM * 2;

    const int tid = threadIdx.x;
    const int wid = tid >> 5, lane = tid & 31;
    const int g = lane >> 2, t = lane & 3;
    const int warp_m = wid >> 1, warp_n = wid & 1;
    const int row0 = blockIdx.y * BM, col0 = blockIdx.x * 64;
    const int kbeg = blockIdx.z * kslice;
    const int niter = kslice / 32;
    C += (size_t)blockIdx.z * M * Nc;

    const u32 sAa = smem_u32(As), sBa = smem_u32(Bs);

    float acc[2][4][4];
#pragma unroll
    for (int mt = 0; mt < 2; mt++)
#pragma unroll
        for (int nt = 0; nt < 4; nt++)
#pragma unroll
            for (int j = 0; j < 4; j++) acc[mt][nt][j] = 0.0f;

    auto issue = [&](int it, int buf) {
        const float* abase = A + (size_t)row0 * K + kbeg + it * 32;
        u32 ad = sAa + buf * BM * STR * 4;
#pragma unroll
        for (int i = 0; i < 4; i++) {
            int c = tid + i * THREADS;          // BM*8 chunks
            int rr = c >> 3, kc = (c & 7) * 4;
            cp16(ad + (rr * STR + kc) * 4, abase + (size_t)rr * K + kc);
        }
        const float* bbase = B + (size_t)col0 * K + kbeg + it * 32;
        u32 bd = sBa + buf * 64 * STR * 4;
#pragma unroll
        for (int i = 0; i < 512 / (BM * 2); i++) {
            int c = tid + i * THREADS;          // 512 chunks
            int rr = c >> 3, kc = (c & 7) * 4;
            cp16(bd + (rr * STR + kc) * 4, bbase + (size_t)rr * K + kc);
        }
        cpcommit();
    };

    issue(0, 0);
    for (int it = 0; it < niter; it++) {
        if (it + 1 < niter) issue(it + 1, (it + 1) & 1);
        if (it + 1 < niter) cpwait1(); else cpwait0();
        __syncthreads();

        const float* Ab = As + (it & 1) * BM * STR;
        const float* Bb = Bs + (it & 1) * 64 * STR;
#pragma unroll
        for (int ks = 0; ks < 4; ks++) {
            u32 af[2][4];
#pragma unroll
            for (int mt = 0; mt < 2; mt++) {
                int rb = warp_m * 32 + mt * 16;
                af[mt][0] = f2tf(Ab[(rb + g) * STR + ks * 8 + t]);
                af[mt][1] = f2tf(Ab[(rb + g + 8) * STR + ks * 8 + t]);
                af[mt][2] = f2tf(Ab[(rb + g) * STR + ks * 8 + t + 4]);
                af[mt][3] = f2tf(Ab[(rb + g + 8) * STR + ks * 8 + t + 4]);
            }
#pragma unroll
            for (int nt = 0; nt < 4; nt++) {
                int nb = warp_n * 32 + nt * 8;
                u32 b0 = f2tf(Bb[(nb + g) * STR + ks * 8 + t]);
                u32 b1 = f2tf(Bb[(nb + g) * STR + ks * 8 + t + 4]);
#pragma unroll
                for (int mt = 0; mt < 2; mt++)
                    mma_tf32(acc[mt][nt][0], acc[mt][nt][1], acc[mt][nt][2], acc[mt][nt][3],
                             af[mt][0], af[mt][1], af[mt][2], af[mt][3], b0, b1);
            }
        }
        __syncthreads();
    }

#pragma unroll
    for (int mt = 0; mt < 2; mt++) {
        int r0 = row0 + warp_m * 32 + mt * 16 + g;
#pragma unroll
        for (int nt = 0; nt < 4; nt++) {
            int c0i = col0 + warp_n * 32 + nt * 8 + 2 * t;
            float b0 = 0.f, b1 = 0.f;
            if (bias) { b0 = bias[c0i]; b1 = bias[c0i + 1]; }
            float v0 = acc[mt][nt][0] + b0, v1 = acc[mt][nt][1] + b1;
            float v2 = acc[mt][nt][2] + b0, v3 = acc[mt][nt][3] + b1;
            if (relu) {
                v0 = fmaxf(v0, 0.f); v1 = fmaxf(v1, 0.f);
                v2 = fmaxf(v2, 0.f); v3 = fmaxf(v3, 0.f);
            }
            if (mode) {   // qkv: pre-round (and pre-scale q) for attention
                float s = (c0i < DD) ? ATT_SCALE : 1.0f;
                v0 = __uint_as_float(f2tf(v0 * s));
                v1 = __uint_as_float(f2tf(v1 * s));
                v2 = __uint_as_float(f2tf(v2 * s));
                v3 = __uint_as_float(f2tf(v3 * s));
            }
            *(float2*)&C[(size_t)r0 * Nc + c0i] = make_float2(v0, v1);
            *(float2*)&C[(size_t)(r0 + 8) * Nc + c0i] = make_float2(v2, v3);
        }
    }
}

// ======================================================================
// Flash attention, tf32 mma, cp.async double-buffered K/V, K-split x2.
// Block = 128 queries x 1 head x half the keys; 256 threads (8 warps,
// each warp one m16 query tile). qkv is pre-rounded tf32 (q pre-scaled),
// so fragment loads are plain LDS with no cvt.
// ======================================================================
#define PSTR 36   // sP row stride (36 mod 32 == 4 -> conflict-free frag reads)

__global__ void __launch_bounds__(256) attn_tc(const float* __restrict__ qkv,
                                               float* __restrict__ pm,
                                               float* __restrict__ pl,
                                               float* __restrict__ pacc)
{
    extern __shared__ float smem[];
    float* sK = smem;                   // [2][64][STR]
    float* sV = smem + 2 * 64 * STR;    // [2][64][STR]
    float* sQ = smem + 4 * 64 * STR;    // [QB][STR], reused as sP [QB][PSTR]
    u32*   sP = (u32*)sQ;

    const int h = blockIdx.y, z = blockIdx.z;
    const int q0 = blockIdx.x * QB;
    const int tid = threadIdx.x;
    const int wid = tid >> 5, lane = tid & 31;
    const int g = lane >> 2, t = lane & 3;
    const int rb = wid * 16;

    const int qoff = h * 32;
    const int koff = DD + h * 32;
    const int voff = 2 * DD + h * 32;
    const int kt_beg = z * KT_PER, kt_end = kt_beg + KT_PER;

    const u32 sKa = smem_u32(sK), sVa = smem_u32(sV), sQa = smem_u32(sQ);

    // stage Q: QB rows x 32 floats = QB*8 chunks, 256 threads -> 4 iters
#pragma unroll
    for (int i = 0; i < QB * 8 / 256; i++) {
        int c = tid + i * 256;
        int rr = c >> 3, kc = (c & 7) * 4;
        cp16(sQa + (rr * STR + kc) * 4, &qkv[(size_t)(q0 + rr) * 384 + qoff + kc]);
    }
    cpcommit();

    auto issueKV = [&](int kt, int buf) {
#pragma unroll
        for (int i = 0; i < 2; i++) {
            int c = tid + i * 256;                  // 512 chunks (64 rows x 8)
            int rr = c >> 3, kc = (c & 7) * 4;
            const float* base = &qkv[(size_t)(kt * 64 + rr) * 384];
            cp16(sKa + (buf * 64 * STR + rr * STR + kc) * 4, base + koff + kc);
            cp16(sVa + (buf * 64 * STR + rr * STR + kc) * 4, base + voff + kc);
        }
        cpcommit();
    };

    issueKV(kt_beg, 0);
    cpwait1();              // Q group done (KV0 may be in flight)
    __syncthreads();

    // Q fragments (already tf32-rounded and 1/sqrt(dh)-scaled)
    u32 qf[4][4];
#pragma unroll
    for (int ks = 0; ks < 4; ks++) {
        qf[ks][0] = __float_as_uint(sQ[(rb + g) * STR + ks * 8 + t]);
        qf[ks][1] = __float_as_uint(sQ[(rb + g + 8) * STR + ks * 8 + t]);
        qf[ks][2] = __float_as_uint(sQ[(rb + g) * STR + ks * 8 + t + 4]);
        qf[ks][3] = __float_as_uint(sQ[(rb + g + 8) * STR + ks * 8 + t + 4]);
    }

    float O[4][4];
#pragma unroll
    for (int nt = 0; nt < 4; nt++)
#pragma unroll
        for (int j = 0; j < 4; j++) O[nt][j] = 0.0f;
    float m_g = -CUDART_INF_F, m_g8 = -CUDART_INF_F;
    float lg = 0.0f, lg8 = 0.0f;

    for (int kt = kt_beg; kt < kt_end; kt++) {
        if (kt + 1 < kt_end) issueKV(kt + 1, (kt + 1) & 1);
        if (kt + 1 < kt_end) cpwait1(); else cpwait0();
        __syncthreads();

        const float* K_ = sK + (kt & 1) * 64 * STR;
        const float* V_ = sV + (kt & 1) * 64 * STR;

        // S = Q K^T (16 x 64 per warp)
        float sc[8][4];
#pragma unroll
        for (int nt = 0; nt < 8; nt++)
#pragma unroll
            for (int j = 0; j < 4; j++) sc[nt][j] = 0.0f;
#pragma unroll
        for (int ks = 0; ks < 4; ks++) {
#pragma unroll
            for (int nt = 0; nt < 8; nt++) {
                u32 b0 = __float_as_uint(K_[(nt * 8 + g) * STR + ks * 8 + t]);
                u32 b1 = __float_as_uint(K_[(nt * 8 + g) * STR + ks * 8 + t + 4]);
                mma_tf32(sc[nt][0], sc[nt][1], sc[nt][2], sc[nt][3],
                         qf[ks][0], qf[ks][1], qf[ks][2], qf[ks][3], b0, b1);
            }
        }

        // row maxima (rows g and g+8)
        float rg = -CUDART_INF_F, rg8 = -CUDART_INF_F;
#pragma unroll
        for (int nt = 0; nt < 8; nt++) {
            rg  = fmaxf(rg,  fmaxf(sc[nt][0], sc[nt][1]));
            rg8 = fmaxf(rg8, fmaxf(sc[nt][2], sc[nt][3]));
        }
        rg  = fmaxf(rg,  __shfl_xor_sync(0xffffffffu, rg, 1));
        rg  = fmaxf(rg,  __shfl_xor_sync(0xffffffffu, rg, 2));
        rg8 = fmaxf(rg8, __shfl_xor_sync(0xffffffffu, rg8, 1));
        rg8 = fmaxf(rg8, __shfl_xor_sync(0xffffffffu, rg8, 2));

        float mng = fmaxf(m_g, rg),   fg  = __expf(m_g - mng);
        float mng8 = fmaxf(m_g8, rg8), fg8 = __expf(m_g8 - mng8);
        m_g = mng; m_g8 = mng8;
        lg *= fg; lg8 *= fg8;
#pragma unroll
        for (int nt = 0; nt < 4; nt++) {
            O[nt][0] *= fg;  O[nt][1] *= fg;
            O[nt][2] *= fg8; O[nt][3] *= fg8;
        }

        // P = exp(S - m) -> sP (tf32 RN); per-warp rows only
#pragma unroll
        for (int nt = 0; nt < 8; nt++) {
            float p0 = __expf(sc[nt][0] - m_g);
            float p1 = __expf(sc[nt][1] - m_g);
            float p2 = __expf(sc[nt][2] - m_g8);
            float p3 = __expf(sc[nt][3] - m_g8);
            lg += p0 + p1; lg8 += p2 + p3;
            int cc = nt * 8 + 2 * t;
            sP[(rb + g) * PSTR + cc] = f2tf(p0);     sP[(rb + g) * PSTR + cc + 1] = f2tf(p1);
            sP[(rb + g + 8) * PSTR + cc] = f2tf(p2); sP[(rb + g + 8) * PSTR + cc + 1] = f2tf(p3);
        }
        __syncwarp();

        // O += P V
#pragma unroll
        for (int ks = 0; ks < 8; ks++) {
            u32 a0 = sP[(rb + g) * PSTR + ks * 8 + t];
            u32 a1 = sP[(rb + g + 8) * PSTR + ks * 8 + t];
            u32 a2 = sP[(rb + g) * PSTR + ks * 8 + t + 4];
            u32 a3 = sP[(rb + g + 8) * PSTR + ks * 8 + t + 4];
#pragma unroll
            for (int nt = 0; nt < 4; nt++) {
                u32 b0 = __float_as_uint(V_[(ks * 8 + t) * STR + nt * 8 + g]);
                u32 b1 = __float_as_uint(V_[(ks * 8 + t + 4) * STR + nt * 8 + g]);
                mma_tf32(O[nt][0], O[nt][1], O[nt][2], O[nt][3],
                         a0, a1, a2, a3, b0, b1);
            }
        }
        __syncthreads();
    }

    // quad-reduce l; write unnormalized partials
    lg  += __shfl_xor_sync(0xffffffffu, lg, 1);
    lg  += __shfl_xor_sync(0xffffffffu, lg, 2);
    lg8 += __shfl_xor_sync(0xffffffffu, lg8, 1);
    lg8 += __shfl_xor_sync(0xffffffffu, lg8, 2);

    const int prow = (z * HH + h) * NN + q0 + rb + g;   // row index in partials
    if (t == 0) {
        pm[prow] = m_g;      pm[prow + 8] = m_g8;
        pl[prow] = lg;       pl[prow + 8] = lg8;
    }
    float* op0 = pacc + (size_t)prow * 32;
    float* op8 = pacc + (size_t)(prow + 8) * 32;
#pragma unroll
    for (int nt = 0; nt < 4; nt++) {
        int cc = nt * 8 + 2 * t;
        *(float2*)&op0[cc] = make_float2(O[nt][0], O[nt][1]);
        *(float2*)&op8[cc] = make_float2(O[nt][2], O[nt][3]);
    }
}

// merge ZSPLIT=2 partials -> ctx (exact flash-attention merge)
__global__ void __launch_bounds__(256) attn_combine(const float* __restrict__ pm,
                                                    const float* __restrict__ pl,
                                                    const float* __restrict__ pacc,
                                                    float* __restrict__ ctx)
{
    int row = blockIdx.x * 8 + (threadIdx.x >> 5);   // 0 .. HH*NN-1
    int lane = threadIdx.x & 31;
    int h = row >> 12, n = row & (NN - 1);
    const int OFF = HH * NN;
    float m0 = pm[row], m1 = pm[OFF + row];
    float mm = fmaxf(m0, m1);
    float w0 = __expf(m0 - mm), w1 = __expf(m1 - mm);
    float l = pl[row] * w0 + pl[OFF + row] * w1;
    float o = pacc[(size_t)row * 32 + lane] * w0
            + pacc[(size_t)(OFF + row) * 32 + lane] * w1;
    ctx[(size_t)n * DD + h * 32 + lane] = o / l;
}

// ---------------- residual + LayerNorm: 2 rows per warp --------------------
// Also zeroes g_cnt (first 16 blocks) so the count kernel can follow.
__global__ void __launch_bounds__(256) ln_kernel(
    const float* __restrict__ x, const float* __restrict__ r,
    const float* __restrict__ g, const float* __restrict__ b,
    float* __restrict__ out)
{
    int w = blockIdx.x * 8 + (threadIdx.x >> 5);    // 0 .. NN/2-1
    int lane = threadIdx.x & 31;
    size_t iA = (size_t)(2 * w) * 32 + lane, iB = iA + 32;
    const float4* x4 = (const float4*)x;
    const float4* r4 = (const float4*)r;
    float4 xa = x4[iA], ra = r4[iA];
    float4 xb = x4[iB], rb_ = r4[iB];
    float4 va = make_float4(xa.x + ra.x, xa.y + ra.y, xa.z + ra.z, xa.w + ra.w);
    float4 vb = make_float4(xb.x + rb_.x, xb.y + rb_.y, xb.z + rb_.z, xb.w + rb_.w);

    float sA = va.x + va.y + va.z + va.w;
    float qA = va.x * va.x + va.y * va.y + va.z * va.z + va.w * va.w;
    float sB = vb.x + vb.y + vb.z + vb.w;
    float qB = vb.x * vb.x + vb.y * vb.y + vb.z * vb.z + vb.w * vb.w;
#pragma unroll
    for (int off = 16; off > 0; off >>= 1) {
        sA += __shfl_xor_sync(0xffffffffu, sA, off);
        qA += __shfl_xor_sync(0xffffffffu, qA, off);
        sB += __shfl_xor_sync(0xffffffffu, sB, off);
        qB += __shfl_xor_sync(0xffffffffu, qB, off);
    }
    float muA = sA * (1.0f / DD), muB = sB * (1.0f / DD);
    float invA = rsqrtf(qA * (1.0f / DD) - muA * muA + LNEPS);
    float invB = rsqrtf(qB * (1.0f / DD) - muB * muB + LNEPS);

    float4 gw = ((const float4*)g)[lane];
    float4 bw = ((const float4*)b)[lane];
    float4 oA, oB;
    oA.x = (va.x - muA) * invA * gw.x + bw.x;
    oA.y = (va.y - muA) * invA * gw.y + bw.y;
    oA.z = (va.z - muA) * invA * gw.z + bw.z;
    oA.w = (va.w - muA) * invA * gw.w + bw.w;
    oB.x = (vb.x - muB) * invB * gw.x + bw.x;
    oB.y = (vb.y - muB) * invB * gw.y + bw.y;
    oB.z = (vb.z - muB) * invB * gw.z + bw.z;
    oB.w = (vb.w - muB) * invB * gw.w + bw.w;
    ((float4*)out)[iA] = oA;
    ((float4*)out)[iB] = oB;

    if (blockIdx.x < 16) g_cnt[blockIdx.x * 256 + threadIdx.x] = 0;
}

__global__ void __launch_bounds__(256) ln_sum4_kernel(
    const float* __restrict__ x, const float* __restrict__ parts,
    const float* __restrict__ fb, const float* __restrict__ g,
    const float* __restrict__ b, float* __restrict__ out)
{
    int row = blockIdx.x * 8 + (threadIdx.x >> 5);
    int lane = threadIdx.x & 31;
    size_t i = (size_t)row * 32 + lane;
    const size_t ps = (size_t)NN * 32;    // float4 stride between partials
    const float4* p4 = (const float4*)parts;
    float4 v = ((const float4*)x)[i];
    float4 fbv = ((const float4*)fb)[lane];
    v.x += fbv.x; v.y += fbv.y; v.z += fbv.z; v.w += fbv.w;
#pragma unroll
    for (int zz = 0; zz < FSPLIT; zz++) {
        float4 p = p4[i + zz * ps];
        v.x += p.x; v.y += p.y; v.z += p.z; v.w += p.w;
    }

    float s = v.x + v.y + v.z + v.w;
    float s2 = v.x * v.x + v.y * v.y + v.z * v.z + v.w * v.w;
#pragma unroll
    for (int off = 16; off > 0; off >>= 1) {
        s  += __shfl_xor_sync(0xffffffffu, s, off);
        s2 += __shfl_xor_sync(0xffffffffu, s2, off);
    }
    float mu = s * (1.0f / DD);
    float var = s2 * (1.0f / DD) - mu * mu;
    float inv = rsqrtf(var + LNEPS);

    float4 gw = ((const float4*)g)[lane];
    float4 bw = ((const float4*)b)[lane];
    float4 o;
    o.x = (v.x - mu) * inv * gw.x + bw.x;
    o.y = (v.y - mu) * inv * gw.y + bw.y;
    o.z = (v.z - mu) * inv * gw.z + bw.z;
    o.w = (v.w - mu) * inv * gw.w + bw.w;
    ((float4*)out)[i] = o;
}

// ---------------- GCN graph preprocessing ---------------------------------
__global__ void count_kernel(const int* __restrict__ dst) {
    int e = blockIdx.x * blockDim.x + threadIdx.x;
    if (e < EE) atomicAdd(&g_cnt[dst[e]], 1);
}
// single-block scan over 4096 counts -> rowptr / fillpos; also dinv
__global__ void scan_kernel() {
    __shared__ int sh[1024];
    int t = threadIdx.x;
    int base = t * 4;
    int c0 = g_cnt[base + 0], c1 = g_cnt[base + 1];
    int c2 = g_cnt[base + 2], c3 = g_cnt[base + 3];
    g_dinv[base + 0] = rsqrtf((float)c0 + 1.0f);
    g_dinv[base + 1] = rsqrtf((float)c1 + 1.0f);
    g_dinv[base + 2] = rsqrtf((float)c2 + 1.0f);
    g_dinv[base + 3] = rsqrtf((float)c3 + 1.0f);
    int local = c0 + c1 + c2 + c3;
    sh[t] = local;
    __syncthreads();
    for (int off = 1; off < 1024; off <<= 1) {
        int v = (t >= off) ? sh[t - off] : 0;
        __syncthreads();
        sh[t] += v;
        __syncthreads();
    }
    int excl = sh[t] - local;
    int p0 = excl, p1 = excl + c0, p2 = p1 + c1, p3 = p2 + c2;
    g_rowptr[base + 0] = p0; g_rowptr[base + 1] = p1;
    g_rowptr[base + 2] = p2; g_rowptr[base + 3] = p3;
    g_fillpos[base + 0] = p0; g_fillpos[base + 1] = p1;
    g_fillpos[base + 2] = p2; g_fillpos[base + 3] = p3;
    if (t == 1023) g_rowptr[NN] = excl + local;
}
__global__ void fill_kernel(const int* __restrict__ src, const int* __restrict__ dst) {
    int e = blockIdx.x * blockDim.x + threadIdx.x;
    if (e < EE) {
        int d = dst[e];
        int pos = atomicAdd(&g_fillpos[d], 1);
        g_col[pos] = src[e];
    }
}

// ---------------- GCN aggregation: gather over CSR, 1-deep prefetch --------
template<int F, bool RELU>
__global__ void gather_kernel(const float* __restrict__ hw,
                              const float* __restrict__ bias,
                              float* __restrict__ out)
{
    constexpr int TPR = F / 4;
    constexpr int RPB = 256 / TPR;
    int tid = threadIdx.x;
    int r = blockIdx.x * RPB + tid / TPR;
    int lane = tid % TPR;
    const float4* hw4 = (const float4*)hw;

    float dr = g_dinv[r];
    float4 acc = hw4[(size_t)r * TPR + lane];
    float selfw = dr * dr;
    acc.x *= selfw; acc.y *= selfw; acc.z *= selfw; acc.w *= selfw;

    int p0 = g_rowptr[r], p1 = g_rowptr[r + 1];
    if (p0 < p1) {
        int s = g_col[p0];
        float4 hv = hw4[(size_t)s * TPR + lane];
        float ds = g_dinv[s];
        for (int p = p0 + 1; p < p1; p++) {
            int s2 = g_col[p];
            float4 hv2 = hw4[(size_t)s2 * TPR + lane];
            float ds2 = g_dinv[s2];
            float nrm = ds * dr;
            acc.x += nrm * hv.x; acc.y += nrm * hv.y;
            acc.z += nrm * hv.z; acc.w += nrm * hv.w;
            hv = hv2; ds = ds2;
        }
        float nrm = ds * dr;
        acc.x += nrm * hv.x; acc.y += nrm * hv.y;
        acc.z += nrm * hv.z; acc.w += nrm * hv.w;
    }
    if (bias) {
        float4 bb = *(const float4*)&bias[lane * 4];
        acc.x += bb.x; acc.y += bb.y; acc.z += bb.z; acc.w += bb.w;
    }
    if (RELU) {
        acc.x = fmaxf(acc.x, 0.f); acc.y = fmaxf(acc.y, 0.f);
        acc.z = fmaxf(acc.z, 0.f); acc.w = fmaxf(acc.w, 0.f);
    }
    *(float4*)&out[(size_t)r * F + lane * 4] = acc;
}

// ---------------- launch ---------------------------------------------------
extern "C" void kernel_launch(void* const* d_in, const int* in_sizes, int n_in,
                              void* d_out, int out_size)
{
    const float* x          = (const float*)d_in[0];
    const int*   edge_index = (const int*)  d_in[1];
    const float* in_proj_w  = (const float*)d_in[2];
    const float* in_proj_b  = (const float*)d_in[3];
    const float* out_proj_w = (const float*)d_in[4];
    const float* out_proj_b = (const float*)d_in[5];
    const float* ln1_g      = (const float*)d_in[6];
    const float* ln1_b      = (const float*)d_in[7];
    const float* ffn_w1     = (const float*)d_in[8];
    const float* ffn_b1     = (const float*)d_in[9];
    const float* ffn_w2     = (const float*)d_in[10];
    const float* ffn_b2     = (const float*)d_in[11];
    const float* ln2_g      = (const float*)d_in[12];
    const float* ln2_b      = (const float*)d_in[13];
    const float* gcn1_w     = (const float*)d_in[14];
    const float* gcn1_b     = (const float*)d_in[15];
    const float* gcn2_w     = (const float*)d_in[16];
    const float* gcn2_b     = (const float*)d_in[17];
    const float* gcn3_w     = (const float*)d_in[18];
    const float* gcn3_b     = (const float*)d_in[19];
    float* out = (float*)d_out;

    const int* src = edge_index;
    const int* dst = edge_index + EE;

    float *p_qkv, *p_ctx, *p_tmp, *p_y, *p_mid, *p_z, *p_f2, *p_hw, *p_h1, *p_h2;
    float *p_pm, *p_pl, *p_pacc;
    cudaGetSymbolAddress((void**)&p_qkv,  g_qkv);
    cudaGetSymbolAddress((void**)&p_ctx,  g_ctx);
    cudaGetSymbolAddress((void**)&p_tmp,  g_tmp);
    cudaGetSymbolAddress((void**)&p_y,    g_y);
    cudaGetSymbolAddress((void**)&p_mid,  g_mid);
    cudaGetSymbolAddress((void**)&p_z,    g_z);
    cudaGetSymbolAddress((void**)&p_f2,   g_f2);
    cudaGetSymbolAddress((void**)&p_hw,   g_hw);
    cudaGetSymbolAddress((void**)&p_h1,   g_h1);
    cudaGetSymbolAddress((void**)&p_h2,   g_h2);
    cudaGetSymbolAddress((void**)&p_pm,   g_pm);
    cudaGetSymbolAddress((void**)&p_pl,   g_pl);
    cudaGetSymbolAddress((void**)&p_pacc, g_pacc);

    const int SM_G128 = (2 * 128 * STR + 2 * 64 * STR) * 4;   // 67584
    const int SM_G64  = (2 * 64 * STR + 2 * 64 * STR) * 4;    // 45056
    const int SM_ATTN = (4 * 64 * STR + QB * STR) * 4;        // 67584 -> 3 blocks/SM

    cudaFuncSetAttribute(gemm_tc<128>, cudaFuncAttributeMaxDynamicSharedMemorySize, SM_G128);
    cudaFuncSetAttribute(gemm_tc<64>,  cudaFuncAttributeMaxDynamicSharedMemorySize, SM_G64);
    cudaFuncSetAttribute(attn_tc,      cudaFuncAttributeMaxDynamicSharedMemorySize, SM_ATTN);

    // ---- transformer encoder layer ----
    gemm_tc<128><<<dim3(6, 32), 256, SM_G128>>>(x, in_proj_w, in_proj_b, p_qkv,
                                                NN, 384, DD, 0, DD, 1);
    attn_tc<<<dim3(NN / QB, HH, ZSPLIT), 256, SM_ATTN>>>(p_qkv, p_pm, p_pl, p_pacc);
    attn_combine<<<HH * NN / 8, 256>>>(p_pm, p_pl, p_pacc, p_ctx);
    gemm_tc<64><<<dim3(2, 64), 128, SM_G64>>>(p_ctx, out_proj_w, out_proj_b, p_tmp,
                                              NN, DD, DD, 0, DD, 0);
    ln_kernel<<<NN / 16, 256>>>(x, p_tmp, ln1_g, ln1_b, p_y);   // also zeroes g_cnt
    gemm_tc<128><<<dim3(32, 32), 256, SM_G128>>>(p_y, ffn_w1, ffn_b1, p_mid,
                                                 NN, DFF, DD, 1, DD, 0);
    gemm_tc<128><<<dim3(2, 32, FSPLIT), 256, SM_G128>>>(p_mid, ffn_w2, nullptr, p_f2,
                                                        NN, DD, DFF, 0, DFF / FSPLIT, 0);
    ln_sum4_kernel<<<NN / 8, 256>>>(p_y, p_f2, ffn_b2, ln2_g, ln2_b, p_z);

    // ---- graph preprocessing (CSR by dst; g_cnt zeroed by ln_kernel) ----
    count_kernel<<<EE / 256, 256>>>(dst);
    scan_kernel<<<1, 1024>>>();          // rowptr + fillpos + dinv
    fill_kernel<<<EE / 256, 256>>>(src, dst);

    // ---- GCN layer 1: aggregate z (128-wide) first, then project ----
    gather_kernel<DD, false><<<NN / 8, 256>>>(p_z, nullptr, p_tmp);
    gemm_tc<64><<<dim3(4, 64), 128, SM_G64>>>(p_tmp, gcn1_w, gcn1_b, p_h1,
                                              NN, HID, DD, 1, DD, 0);

    // ---- GCN layer 2: project then aggregate (bias+relu in gather) ----
    gemm_tc<64><<<dim3(4, 64), 128, SM_G64>>>(p_h1, gcn2_w, nullptr, p_hw,
                                              NN, HID, HID, 0, HID, 0);
    gather_kernel<HID, true><<<NN / 4, 256>>>(p_hw, gcn2_b, p_h2);

    // ---- GCN layer 3: project (64-wide) then aggregate ----
    gemm_tc<64><<<dim3(1, 64), 128, SM_G64>>>(p_h2, gcn3_w, nullptr, p_hw,
                                              NN, OUTD, HID, 0, HID, 0);
    gather_kernel<OUTD, false><<<NN / 16, 256>>>(p_hw, gcn3_b, out);
}